// round 11
// baseline (speedup 1.0000x reference)
#include <cuda_runtime.h>
#include <cuda_bf16.h>
#include <math.h>

#define Bb   8
#define Cc   512
#define Nn   4096
#define NHh  8
#define Dd   64
#define EPSf 1e-5f

typedef __nv_bfloat16 bf16;

// ---------------- scratch (device globals; no allocation) ----------------
__device__ float g_qn  [Bb*Cc*Nn];        // layernormed q, (B,C,N) fp32 (residual)
__device__ bf16  g_qnt [Bb*Nn*Cc];        // layernormed q, token-major (B,N,C) bf16
__device__ bf16  g_kvnt[Bb*Nn*Cc];        // layernormed kv, token-major bf16
__device__ bf16  g_Wh  [4*Cc*Cc];         // Wq,Wk,Wv,Wo in bf16
__device__ bf16  g_Qh  [Bb*NHh*Nn*Dd];    // (B,NH,N,D) rope applied
__device__ bf16  g_Kh  [Bb*NHh*Nn*Dd];
__device__ bf16  g_Vh  [Bb*NHh*Nn*Dd];
__device__ bf16  g_AOh [Bb*Nn*Cc];        // attention out, (B,N,C)
__device__ float g_sin [Nn*32];
__device__ float g_cos [Nn*32];
__device__ float g_bias[NHh*64*64];       // (NH, Ws, Ws)

// ---------------- helpers ----------------
__device__ __forceinline__ unsigned sptr(const void* p) {
    return (unsigned)__cvta_generic_to_shared(p);
}
#define CP16(d, s)  asm volatile("cp.async.cg.shared.global [%0], [%1], 16;" :: "r"(d), "l"(s))
#define CP_COMMIT() asm volatile("cp.async.commit_group;")
#define CP_WAIT(n)  asm volatile("cp.async.wait_group %0;" :: "n"(n))

__device__ __forceinline__ void ldsm_x4(unsigned& r0, unsigned& r1, unsigned& r2, unsigned& r3, unsigned a) {
    asm volatile("ldmatrix.sync.aligned.m8n8.x4.shared.b16 {%0,%1,%2,%3}, [%4];"
                 : "=r"(r0), "=r"(r1), "=r"(r2), "=r"(r3) : "r"(a));
}
__device__ __forceinline__ void ldsm_x4t(unsigned& r0, unsigned& r1, unsigned& r2, unsigned& r3, unsigned a) {
    asm volatile("ldmatrix.sync.aligned.m8n8.x4.trans.shared.b16 {%0,%1,%2,%3}, [%4];"
                 : "=r"(r0), "=r"(r1), "=r"(r2), "=r"(r3) : "r"(a));
}
__device__ __forceinline__ void mma_bf16(float* c, const unsigned* a, const unsigned* b) {
    asm volatile(
        "mma.sync.aligned.m16n8k16.row.col.f32.bf16.bf16.f32 "
        "{%0,%1,%2,%3}, {%4,%5,%6,%7}, {%8,%9}, {%0,%1,%2,%3};"
        : "+f"(c[0]), "+f"(c[1]), "+f"(c[2]), "+f"(c[3])
        : "r"(a[0]), "r"(a[1]), "r"(a[2]), "r"(a[3]), "r"(b[0]), "r"(b[1]));
}
__device__ __forceinline__ unsigned packbf(float lo, float hi) {
    unsigned d; asm("cvt.rn.bf16x2.f32 %0, %1, %2;" : "=r"(d) : "f"(hi), "f"(lo)); return d;
}

// ============ prep: weight cvt + rope table + bias table, one launch ========
__global__ __launch_bounds__(256) void prep_kernel(const float* __restrict__ w0,
                                                   const float* __restrict__ w1,
                                                   const float* __restrict__ w2,
                                                   const float* __restrict__ w3,
                                                   const float* __restrict__ table)
{
    int blk = blockIdx.x;
    if (blk < 1024) {                        // wcvt: 1024*256 = 262144 = Cc*Cc
        int i = blk * 256 + threadIdx.x;
        g_Wh[0*Cc*Cc + i] = __float2bfloat16_rn(w0[i]);
        g_Wh[1*Cc*Cc + i] = __float2bfloat16_rn(w1[i]);
        g_Wh[2*Cc*Cc + i] = __float2bfloat16_rn(w2[i]);
        g_Wh[3*Cc*Cc + i] = __float2bfloat16_rn(w3[i]);
    } else if (blk < 1536) {                 // rope: 512*256 = 131072 = Nn*32
        int i = (blk - 1024) * 256 + threadIdx.x;
        int n = i >> 5, k = i & 31;
        float invf = exp2f(-(float)k * (13.287712379549449f / 32.0f));
        float ang  = (float)n * invf;
        float sv, cv;  sincosf(ang, &sv, &cv);
        g_sin[i] = sv;  g_cos[i] = cv;
    } else {                                 // bias: 128*256 = 32768 = NH*4096
        int i = (blk - 1536) * 256 + threadIdx.x;
        int h  = i >> 12;
        int qi = (i >> 6) & 63, ki = i & 63;
        int dh = (qi >> 3) - (ki >> 3) + 7;
        int dw = (qi & 7)  - (ki & 7)  + 7;
        g_bias[i] = table[(dh * 15 + dw) * NHh + h];
    }
}

// ====== layernorm: 32 tokens x 512 C per block, smem transpose ======
template<bool F32OUT>
__global__ __launch_bounds__(256) void ln_kernel(const float* __restrict__ x,
                                                 const float* __restrict__ g,
                                                 const float* __restrict__ bt,
                                                 float* __restrict__ yf,
                                                 bf16* __restrict__ yh)
{
    extern __shared__ float sm[];
    float* sx  = sm;                  // [512][33]
    float* ps  = sm + 512*33;         // [8][32]
    float* ps2 = ps + 256;            // [8][32]
    float* smu = ps2 + 256;           // [32]
    float* sin_ = smu + 32;           // [32] inv

    const int blk = blockIdx.x;       // 0..1023
    const int b   = blk >> 7;
    const int n0  = (blk & 127) * 32;
    const int tid = threadIdx.x;
    const int t   = tid & 31;
    const int cp  = tid >> 5;

    const float* xb = x + (size_t)b*Cc*Nn + n0;
    float s = 0.f, s2 = 0.f;
#pragma unroll 8
    for (int it = 0; it < 64; it++) {
        int c = it*8 + cp;
        float v = xb[(size_t)c*Nn + t];
        sx[c*33 + t] = v;
        s += v;  s2 = fmaf(v, v, s2);
    }
    ps[cp*32 + t] = s;  ps2[cp*32 + t] = s2;
    __syncthreads();
    if (tid < 32) {
        float a = 0.f, a2 = 0.f;
#pragma unroll
        for (int k = 0; k < 8; k++) { a += ps[k*32 + tid]; a2 += ps2[k*32 + tid]; }
        float mu  = a * (1.f/Cc);
        float var = a2 * (1.f/Cc) - mu*mu;
        smu[tid]  = mu;
        sin_[tid] = rsqrtf(var + EPSf);
    }
    __syncthreads();

    const float mu = smu[t], inv = sin_[t];
    float* yfb = F32OUT ? (yf + (size_t)b*Cc*Nn + n0) : nullptr;
#pragma unroll 8
    for (int it = 0; it < 64; it++) {
        int c = it*8 + cp;
        float o = (sx[c*33 + t] - mu) * inv * g[c] + bt[c];
        sx[c*33 + t] = o;
        if (F32OUT) yfb[(size_t)c*Nn + t] = o;
    }
    __syncthreads();

    {
        int tok = tid & 31, cb = (tid >> 5) * 64;
        union { uint4 q[8]; unsigned u[32]; } buf;
#pragma unroll
        for (int i = 0; i < 32; i++) {
            float v0 = sx[(cb + 2*i    )*33 + tok];
            float v1 = sx[(cb + 2*i + 1)*33 + tok];
            buf.u[i] = packbf(v0, v1);
        }
        uint4* dst = (uint4*)(yh + ((size_t)b*Nn + n0 + tok)*Cc + cb);
#pragma unroll
        for (int i = 0; i < 8; i++) dst[i] = buf.q[i];
    }
}

// ================= bf16 GEMM (NT): merged Q/K/V projections ==================
// Block tile 128m x 256n, BK=64, warp tile 64x64 (8 warps, 2m x 4n).
// 2-stage cp.async double buffer. blockIdx.y 0..5: seg = y>>1, j0 = (y&1)*256.
// stage layout: A [128][72] then B [256][72]; stage stride 27648 bf16.
__global__ __launch_bounds__(256, 1) void gemm_qkv_bf(const bf16* __restrict__ Aq,
                                                      const bf16* __restrict__ Akv,
                                                      const float* __restrict__ bq,
                                                      const float* __restrict__ bk,
                                                      const float* __restrict__ bv,
                                                      bf16* __restrict__ outQ,
                                                      bf16* __restrict__ outK,
                                                      bf16* __restrict__ outV)
{
    extern __shared__ __align__(16) bf16 smraw[];

    const int seg = blockIdx.y >> 1;            // 0=Q 1=K 2=V
    const bf16*  A    = seg ? Akv : Aq;
    const bf16*  W    = g_Wh + (size_t)seg*Cc*Cc;
    const float* bias = (seg == 0) ? bq : (seg == 1) ? bk : bv;
    bf16*        out  = (seg == 0) ? outQ : (seg == 1) ? outK : outV;
    const bool   rope = (seg < 2);
    const int j0 = (blockIdx.y & 1) * 256;

    const int t0 = blockIdx.x * 128;
    const int b  = t0 >> 12;
    const int n0 = t0 & 4095;
    const int tid = threadIdx.x;
    const int lane = tid & 31, wid = tid >> 5;
    const int wm = wid & 1, wn = wid >> 1;
    const int r = lane >> 2, q = lane & 3;
    const int grp = lane >> 3, lr = lane & 7;

    float acc[4][8][4];
#pragma unroll
    for (int i = 0; i < 4; i++)
#pragma unroll
        for (int j = 0; j < 8; j++)
#pragma unroll
            for (int k = 0; k < 4; k++) acc[i][j][k] = 0.f;

#define LOAD_QKV(S, BUF)                                                        \
    {                                                                           \
        bf16* Ad = smraw + (BUF)*27648;                                         \
        bf16* Bd = Ad + 9216;                                                   \
        int c0 = (S)*64;                                                        \
        _Pragma("unroll")                                                       \
        for (int u = 0; u < 4; u++) {                                           \
            int flat = u*256 + tid;                                             \
            int m = flat >> 3, kc = flat & 7;                                   \
            CP16(sptr(Ad + m*72 + kc*8),                                        \
                 A + (size_t)(t0+m)*Cc + c0 + kc*8);                            \
        }                                                                       \
        _Pragma("unroll")                                                       \
        for (int u = 0; u < 8; u++) {                                           \
            int flat = u*256 + tid;                                             \
            int n = flat >> 3, kc = flat & 7;                                   \
            CP16(sptr(Bd + n*72 + kc*8),                                        \
                 W + (size_t)(j0+n)*Cc + c0 + kc*8);                            \
        }                                                                       \
    }

    LOAD_QKV(0, 0); CP_COMMIT();

#pragma unroll 1
    for (int s = 0; s < 8; s++) {
        CP_WAIT(0);
        __syncthreads();
        if (s < 7) { LOAD_QKV(s+1, (s+1)&1); CP_COMMIT(); }

        const bf16* Ac = smraw + (s&1)*27648;
        const bf16* Bc = Ac + 9216;
#pragma unroll
        for (int kk = 0; kk < 4; kk++) {
            unsigned af[4][4], bfr[8][2];
#pragma unroll
            for (int i = 0; i < 4; i++) {
                int m  = wm*64 + 16*i + ((grp & 1) ? 8 : 0) + lr;
                int ka = (grp & 2) ? 8 : 0;
                ldsm_x4(af[i][0], af[i][1], af[i][2], af[i][3],
                        sptr(Ac + m*72 + kk*16 + ka));
            }
#pragma unroll
            for (int jg = 0; jg < 4; jg++) {
                int n = wn*64 + jg*16 + ((grp & 2) ? 8 : 0) + lr;
                int ka = (grp & 1) ? 8 : 0;
                ldsm_x4(bfr[jg*2][0], bfr[jg*2][1], bfr[jg*2+1][0], bfr[jg*2+1][1],
                        sptr(Bc + n*72 + kk*16 + ka));
            }
#pragma unroll
            for (int i = 0; i < 4; i++)
#pragma unroll
                for (int j = 0; j < 8; j++)
                    mma_bf16(acc[i][j], af[i], bfr[j]);
        }
    }
#undef LOAD_QKV

    // ---- epilogue: bias (+ RoPE, fp32), store bf16 ----
#pragma unroll
    for (int i = 0; i < 4; i++) {
        int ntok = n0 + wm*64 + 16*i + r;
#pragma unroll
        for (int j = 0; j < 8; j++) {
            int jj = j0 + wn*64 + 8*j + 2*q;
            int hh = jj >> 6;
            int d  = jj & 63;                  // even
            float bv0 = bias[jj], bv1 = bias[jj+1];
#pragma unroll
            for (int half = 0; half < 2; half++) {
                int n = ntok + 8*half;
                float v0 = acc[i][j][2*half+0] + bv0;
                float v1 = acc[i][j][2*half+1] + bv1;
                float x, y;
                if (rope) {
                    int p = (n << 5) + (d >> 1);
                    float sv = g_sin[p], cv = g_cos[p];
                    x = v0*cv - v1*sv;
                    y = v0*sv + v1*cv;
                } else { x = v0; y = v1; }
                *(__nv_bfloat162*)&out[(((size_t)b*NHh + hh)*Nn + n)*Dd + d] =
                    __floats2bfloat162_rn(x, y);
            }
        }
    }
}

// ================= bf16 GEMM (NT): output projection, 128x256 tile ==========
__global__ __launch_bounds__(256, 1) void gemm_o_bf(const bf16* __restrict__ A,
                                                    const bf16* __restrict__ W,
                                                    const float* __restrict__ bias,
                                                    const float* __restrict__ resid,
                                                    float* __restrict__ out)
{
    extern __shared__ __align__(16) bf16 smraw[];

    const int t0 = blockIdx.x * 128;
    const int b  = t0 >> 12;
    const int n0 = t0 & 4095;
    const int j0 = blockIdx.y * 256;
    const int tid = threadIdx.x;
    const int lane = tid & 31, wid = tid >> 5;
    const int wm = wid & 1, wn = wid >> 1;
    const int r = lane >> 2, q = lane & 3;
    const int grp = lane >> 3, lr = lane & 7;

    float acc[4][8][4];
#pragma unroll
    for (int i = 0; i < 4; i++)
#pragma unroll
        for (int j = 0; j < 8; j++)
#pragma unroll
            for (int k = 0; k < 4; k++) acc[i][j][k] = 0.f;

#define LOAD_O(S, BUF)                                                          \
    {                                                                           \
        bf16* Ad = smraw + (BUF)*27648;                                         \
        bf16* Bd = Ad + 9216;                                                   \
        int c0 = (S)*64;                                                        \
        _Pragma("unroll")                                                       \
        for (int u = 0; u < 4; u++) {                                           \
            int flat = u*256 + tid;                                             \
            int m = flat >> 3, kc = flat & 7;                                   \
            CP16(sptr(Ad + m*72 + kc*8),                                        \
                 A + (size_t)(t0+m)*Cc + c0 + kc*8);                            \
        }                                                                       \
        _Pragma("unroll")                                                       \
        for (int u = 0; u < 8; u++) {                                           \
            int flat = u*256 + tid;                                             \
            int n = flat >> 3, kc = flat & 7;                                   \
            CP16(sptr(Bd + n*72 + kc*8),                                        \
                 W + (size_t)(j0+n)*Cc + c0 + kc*8);                            \
        }                                                                       \
    }

    LOAD_O(0, 0); CP_COMMIT();

#pragma unroll 1
    for (int s = 0; s < 8; s++) {
        CP_WAIT(0);
        __syncthreads();
        if (s < 7) { LOAD_O(s+1, (s+1)&1); CP_COMMIT(); }

        const bf16* Ac = smraw + (s&1)*27648;
        const bf16* Bc = Ac + 9216;
#pragma unroll
        for (int kk = 0; kk < 4; kk++) {
            unsigned af[4][4], bfr[8][2];
#pragma unroll
            for (int i = 0; i < 4; i++) {
                int m  = wm*64 + 16*i + ((grp & 1) ? 8 : 0) + lr;
                int ka = (grp & 2) ? 8 : 0;
                ldsm_x4(af[i][0], af[i][1], af[i][2], af[i][3],
                        sptr(Ac + m*72 + kk*16 + ka));
            }
#pragma unroll
            for (int jg = 0; jg < 4; jg++) {
                int n = wn*64 + jg*16 + ((grp & 2) ? 8 : 0) + lr;
                int ka = (grp & 1) ? 8 : 0;
                ldsm_x4(bfr[jg*2][0], bfr[jg*2][1], bfr[jg*2+1][0], bfr[jg*2+1][1],
                        sptr(Bc + n*72 + kk*16 + ka));
            }
#pragma unroll
            for (int i = 0; i < 4; i++)
#pragma unroll
                for (int j = 0; j < 8; j++)
                    mma_bf16(acc[i][j], af[i], bfr[j]);
        }
    }
#undef LOAD_O

    // ---- epilogue: bias + residual (fp32), write (B,C,N) ----
#pragma unroll
    for (int j = 0; j < 8; j++) {
        int jj0 = j0 + wn*64 + 8*j + 2*q;
#pragma unroll
        for (int col = 0; col < 2; col++) {
            int jj = jj0 + col;
            float bj = bias[jj];
            size_t rowbase = ((size_t)b*Cc + jj)*Nn;
#pragma unroll
            for (int i = 0; i < 4; i++) {
#pragma unroll
                for (int half = 0; half < 2; half++) {
                    int n = n0 + wm*64 + 16*i + r + 8*half;
                    size_t o = rowbase + n;
                    out[o] = acc[i][j][2*half + col] + bj + resid[o];
                }
            }
        }
    }
}

// ---------------- windowed attention (bf16 mma), 1 block per (head, window) --
__global__ __launch_bounds__(128) void attn_bf()
{
    __shared__ __align__(16) bf16 Qs[64*72];
    __shared__ __align__(16) bf16 Ks[64*72];
    __shared__ __align__(16) bf16 Vs[64*72];

    const int bx  = blockIdx.x;     // 0..4095
    const int h   = bx >> 9;
    const int win = bx & 511;
    const int b   = win >> 6;
    const int w   = win & 63;
    const int wy  = w >> 3, wx = w & 7;
    const int tid = threadIdx.x;
    const int lane = tid & 31, wid = tid >> 5;
    const int grp = lane >> 3, lr = lane & 7;

    {
        int t  = tid & 63;
        int c2 = tid >> 6;
        int n_t = ((wy*8 + (t >> 3)) << 6) + wx*8 + (t & 7);
        size_t base = (((size_t)b*NHh + h)*Nn + n_t)*Dd;
#pragma unroll
        for (int u = 0; u < 4; u++) {
            int off = c2*32 + u*8;
            uint4 qv = *(const uint4*)((const char*)g_Qh + (base + off)*2);
            uint4 kv = *(const uint4*)((const char*)g_Kh + (base + off)*2);
            uint4 vv = *(const uint4*)((const char*)g_Vh + (base + off)*2);
            *(uint4*)((char*)Qs + (t*72 + off)*2) = qv;
            *(uint4*)((char*)Ks + (t*72 + off)*2) = kv;
            *(uint4*)((char*)Vs + (t*72 + off)*2) = vv;
        }
    }
    __syncthreads();

    const int m0 = wid * 16;

    unsigned af[4][4];
#pragma unroll
    for (int kk = 0; kk < 4; kk++) {
        int m  = m0 + ((grp & 1) ? 8 : 0) + lr;
        int ka = (grp & 2) ? 8 : 0;
        ldsm_x4(af[kk][0], af[kk][1], af[kk][2], af[kk][3],
                sptr(Qs + m*72 + kk*16 + ka));
    }

    float s[8][4];
#pragma unroll
    for (int j = 0; j < 8; j++)
#pragma unroll
        for (int c = 0; c < 4; c++) s[j][c] = 0.f;

#pragma unroll
    for (int kk = 0; kk < 4; kk++) {
        unsigned bfr[8][2];
#pragma unroll
        for (int jg = 0; jg < 4; jg++) {
            int n  = jg*16 + ((grp & 2) ? 8 : 0) + lr;
            int ka = (grp & 1) ? 8 : 0;
            ldsm_x4(bfr[jg*2][0], bfr[jg*2][1], bfr[jg*2+1][0], bfr[jg*2+1][1],
                    sptr(Ks + n*72 + kk*16 + ka));
        }
#pragma unroll
        for (int j = 0; j < 8; j++)
            mma_bf16(s[j], af[kk], bfr[j]);
    }

    const float* bh = g_bias + (h << 12);
    const int row0 = m0 + (lane >> 2);
    const int col0 = 2 * (lane & 3);
    float mx0 = -1e30f, mx1 = -1e30f;
#pragma unroll
    for (int j = 0; j < 8; j++) {
        float2 b0 = *(const float2*)(bh + row0*64 + 8*j + col0);
        float2 b1 = *(const float2*)(bh + (row0+8)*64 + 8*j + col0);
        s[j][0] = fmaf(s[j][0], 0.125f, b0.x);
        s[j][1] = fmaf(s[j][1], 0.125f, b0.y);
        s[j][2] = fmaf(s[j][2], 0.125f, b1.x);
        s[j][3] = fmaf(s[j][3], 0.125f, b1.y);
        mx0 = fmaxf(mx0, fmaxf(s[j][0], s[j][1]));
        mx1 = fmaxf(mx1, fmaxf(s[j][2], s[j][3]));
    }
    mx0 = fmaxf(mx0, __shfl_xor_sync(0xffffffffu, mx0, 1));
    mx0 = fmaxf(mx0, __shfl_xor_sync(0xffffffffu, mx0, 2));
    mx1 = fmaxf(mx1, __shfl_xor_sync(0xffffffffu, mx1, 1));
    mx1 = fmaxf(mx1, __shfl_xor_sync(0xffffffffu, mx1, 2));

    float sum0 = 0.f, sum1 = 0.f;
#pragma unroll
    for (int j = 0; j < 8; j++) {
        s[j][0] = __expf(s[j][0] - mx0);
        s[j][1] = __expf(s[j][1] - mx0);
        s[j][2] = __expf(s[j][2] - mx1);
        s[j][3] = __expf(s[j][3] - mx1);
        sum0 += s[j][0] + s[j][1];
        sum1 += s[j][2] + s[j][3];
    }
    sum0 += __shfl_xor_sync(0xffffffffu, sum0, 1);
    sum0 += __shfl_xor_sync(0xffffffffu, sum0, 2);
    sum1 += __shfl_xor_sync(0xffffffffu, sum1, 1);
    sum1 += __shfl_xor_sync(0xffffffffu, sum1, 2);
    float inv0 = 1.f / sum0, inv1 = 1.f / sum1;

    float o[8][4];
#pragma unroll
    for (int j = 0; j < 8; j++)
#pragma unroll
        for (int c = 0; c < 4; c++) o[j][c] = 0.f;

#pragma unroll
    for (int kk = 0; kk < 4; kk++) {
        unsigned pa[4];
        pa[0] = packbf(s[2*kk  ][0], s[2*kk  ][1]);
        pa[1] = packbf(s[2*kk  ][2], s[2*kk  ][3]);
        pa[2] = packbf(s[2*kk+1][0], s[2*kk+1][1]);
        pa[3] = packbf(s[2*kk+1][2], s[2*kk+1][3]);
        unsigned vb[8][2];
#pragma unroll
        for (int jg = 0; jg < 4; jg++) {
            int rowk = kk*16 + ((grp & 1) ? 8 : 0) + lr;
            int cold = jg*16 + ((grp & 2) ? 8 : 0);
            ldsm_x4t(vb[jg*2][0], vb[jg*2][1], vb[jg*2+1][0], vb[jg*2+1][1],
                     sptr(Vs + rowk*72 + cold));
        }
#pragma unroll
        for (int j = 0; j < 8; j++)
            mma_bf16(o[j], pa, vb[j]);
    }

    {
        int tA = row0, tB = row0 + 8;
        int nA = ((wy*8 + (tA >> 3)) << 6) + wx*8 + (tA & 7);
        int nB = ((wy*8 + (tB >> 3)) << 6) + wx*8 + (tB & 7);
        size_t baseA = ((size_t)b*Nn + nA)*Cc + (h << 6);
        size_t baseB = ((size_t)b*Nn + nB)*Cc + (h << 6);
#pragma unroll
        for (int j = 0; j < 8; j++) {
            int d = 8*j + col0;
            *(__nv_bfloat162*)&g_AOh[baseA + d] =
                __floats2bfloat162_rn(o[j][0]*inv0, o[j][1]*inv0);
            *(__nv_bfloat162*)&g_AOh[baseB + d] =
                __floats2bfloat162_rn(o[j][2]*inv1, o[j][3]*inv1);
        }
    }
}

// ---------------- host side ----------------
extern "C" void kernel_launch(void* const* d_in, const int* in_sizes, int n_in,
                              void* d_out, int out_size)
{
    const float* q    = (const float*)d_in[0];
    const float* kv   = (const float*)d_in[1];
    const float* gq   = (const float*)d_in[2];
    const float* bqln = (const float*)d_in[3];
    const float* gkv  = (const float*)d_in[4];
    const float* bkvln= (const float*)d_in[5];
    const float* Wq   = (const float*)d_in[6];
    const float* bq   = (const float*)d_in[7];
    const float* Wk   = (const float*)d_in[8];
    const float* bk   = (const float*)d_in[9];
    const float* Wv   = (const float*)d_in[10];
    const float* bv   = (const float*)d_in[11];
    const float* Wo   = (const float*)d_in[12];
    const float* bo   = (const float*)d_in[13];
    const float* tbl  = (const float*)d_in[14];
    float* out = (float*)d_out;

    void* p;
    cudaGetSymbolAddress(&p, g_qn);   float* qn   = (float*)p;
    cudaGetSymbolAddress(&p, g_qnt);  bf16* qnt   = (bf16*)p;
    cudaGetSymbolAddress(&p, g_kvnt); bf16* kvnt  = (bf16*)p;
    cudaGetSymbolAddress(&p, g_Wh);   bf16* Wh    = (bf16*)p;
    cudaGetSymbolAddress(&p, g_Qh);   bf16* Qb    = (bf16*)p;
    cudaGetSymbolAddress(&p, g_Kh);   bf16* Kb    = (bf16*)p;
    cudaGetSymbolAddress(&p, g_Vh);   bf16* Vb    = (bf16*)p;
    cudaGetSymbolAddress(&p, g_AOh);  bf16* AO    = (bf16*)p;

    const int SMEM_LN = (512*33 + 512 + 64) * 4;     // 69888 B
    const int SMEM_G  = 2 * 27648 * 2;               // 110592 B
    static int smem_set = 0;
    if (!smem_set) {
        cudaFuncSetAttribute(ln_kernel<true>,  cudaFuncAttributeMaxDynamicSharedMemorySize, SMEM_LN);
        cudaFuncSetAttribute(ln_kernel<false>, cudaFuncAttributeMaxDynamicSharedMemorySize, SMEM_LN);
        cudaFuncSetAttribute(gemm_qkv_bf,      cudaFuncAttributeMaxDynamicSharedMemorySize, SMEM_G);
        cudaFuncSetAttribute(gemm_o_bf,        cudaFuncAttributeMaxDynamicSharedMemorySize, SMEM_G);
        smem_set = 1;
    }

    // 0: weight cvt + rope + bias tables (one launch)
    prep_kernel<<<1664, 256>>>(Wq, Wk, Wv, Wo, tbl);

    // 1,2: layernorms (token-major bf16 out; q also fp32 channel-major)
    ln_kernel<true ><<<1024, 256, SMEM_LN>>>(q,  gq,  bqln,  qn, qnt);
    ln_kernel<false><<<1024, 256, SMEM_LN>>>(kv, gkv, bkvln, qn, kvnt);

    // 3: merged Q/K/V projections (rope fused for Q and K)
    gemm_qkv_bf<<<dim3(256, 6), 256, SMEM_G>>>(qnt, kvnt, bq, bk, bv, Qb, Kb, Vb);

    // 4: windowed attention
    attn_bf<<<NHh * Bb * 64, 128>>>();

    // 5: output projection + bias + residual -> (B,C,H,W)
    gemm_o_bf<<<dim3(256, 2), 256, SMEM_G>>>(AO, Wh + 3*Cc*Cc, bo, qn, out);
}

// round 12
// speedup vs baseline: 1.0674x; 1.0674x over previous
#include <cuda_runtime.h>
#include <cuda_bf16.h>
#include <math.h>

#define Bb   8
#define Cc   512
#define Nn   4096
#define NHh  8
#define Dd   64
#define EPSf 1e-5f

typedef __nv_bfloat16 bf16;

// ---------------- scratch (device globals; no allocation) ----------------
__device__ float g_qn  [Bb*Cc*Nn];        // layernormed q, (B,C,N) fp32 (residual)
__device__ bf16  g_qnt [Bb*Nn*Cc];        // layernormed q, token-major (B,N,C) bf16
__device__ bf16  g_kvnt[Bb*Nn*Cc];        // layernormed kv, token-major bf16
__device__ bf16  g_Wh  [4*Cc*Cc];         // Wq,Wk,Wv,Wo in bf16
__device__ bf16  g_Qh  [Bb*NHh*Nn*Dd];    // (B,NH,N,D) rope applied
__device__ bf16  g_Kh  [Bb*NHh*Nn*Dd];
__device__ bf16  g_Vh  [Bb*NHh*Nn*Dd];
__device__ bf16  g_AOh [Bb*Nn*Cc];        // attention out, (B,N,C)
__device__ float g_sin [Nn*32];
__device__ float g_cos [Nn*32];
__device__ float g_bias[NHh*64*64];       // (NH, Ws, Ws)

// ---------------- helpers ----------------
__device__ __forceinline__ unsigned sptr(const void* p) {
    return (unsigned)__cvta_generic_to_shared(p);
}
#define CP16(d, s)  asm volatile("cp.async.cg.shared.global [%0], [%1], 16;" :: "r"(d), "l"(s))
#define CP_COMMIT() asm volatile("cp.async.commit_group;")
#define CP_WAIT(n)  asm volatile("cp.async.wait_group %0;" :: "n"(n))

__device__ __forceinline__ void ldsm_x4(unsigned& r0, unsigned& r1, unsigned& r2, unsigned& r3, unsigned a) {
    asm volatile("ldmatrix.sync.aligned.m8n8.x4.shared.b16 {%0,%1,%2,%3}, [%4];"
                 : "=r"(r0), "=r"(r1), "=r"(r2), "=r"(r3) : "r"(a));
}
__device__ __forceinline__ void ldsm_x4t(unsigned& r0, unsigned& r1, unsigned& r2, unsigned& r3, unsigned a) {
    asm volatile("ldmatrix.sync.aligned.m8n8.x4.trans.shared.b16 {%0,%1,%2,%3}, [%4];"
                 : "=r"(r0), "=r"(r1), "=r"(r2), "=r"(r3) : "r"(a));
}
__device__ __forceinline__ void mma_bf16(float* c, const unsigned* a, const unsigned* b) {
    asm volatile(
        "mma.sync.aligned.m16n8k16.row.col.f32.bf16.bf16.f32 "
        "{%0,%1,%2,%3}, {%4,%5,%6,%7}, {%8,%9}, {%0,%1,%2,%3};"
        : "+f"(c[0]), "+f"(c[1]), "+f"(c[2]), "+f"(c[3])
        : "r"(a[0]), "r"(a[1]), "r"(a[2]), "r"(a[3]), "r"(b[0]), "r"(b[1]));
}
__device__ __forceinline__ unsigned packbf(float lo, float hi) {
    unsigned d; asm("cvt.rn.bf16x2.f32 %0, %1, %2;" : "=r"(d) : "f"(hi), "f"(lo)); return d;
}

// ====== fused pre-stage: prep (weights/rope/bias) + both layernorms =========
// blocks [0,1664): prep; [1664,2688): LN(q); [2688,3712): LN(kv).
__global__ __launch_bounds__(256) void fused_pre(const float* __restrict__ q,
                                                 const float* __restrict__ kv,
                                                 const float* __restrict__ gq,
                                                 const float* __restrict__ bqln,
                                                 const float* __restrict__ gkv,
                                                 const float* __restrict__ bkvln,
                                                 const float* __restrict__ w0,
                                                 const float* __restrict__ w1,
                                                 const float* __restrict__ w2,
                                                 const float* __restrict__ w3,
                                                 const float* __restrict__ table,
                                                 float* __restrict__ qn,
                                                 bf16* __restrict__ qnt,
                                                 bf16* __restrict__ kvnt)
{
    extern __shared__ float sm[];
    const int blk0 = blockIdx.x;
    const int tid  = threadIdx.x;

    if (blk0 < 1664) {
        // ---------------- prep ----------------
        int blk = blk0;
        if (blk < 1024) {                        // wcvt
            int i = blk * 256 + tid;
            g_Wh[0*Cc*Cc + i] = __float2bfloat16_rn(w0[i]);
            g_Wh[1*Cc*Cc + i] = __float2bfloat16_rn(w1[i]);
            g_Wh[2*Cc*Cc + i] = __float2bfloat16_rn(w2[i]);
            g_Wh[3*Cc*Cc + i] = __float2bfloat16_rn(w3[i]);
        } else if (blk < 1536) {                 // rope
            int i = (blk - 1024) * 256 + tid;
            int n = i >> 5, k = i & 31;
            float invf = exp2f(-(float)k * (13.287712379549449f / 32.0f));
            float ang  = (float)n * invf;
            float sv, cv;  sincosf(ang, &sv, &cv);
            g_sin[i] = sv;  g_cos[i] = cv;
        } else {                                 // bias
            int i = (blk - 1536) * 256 + tid;
            int h  = i >> 12;
            int qi = (i >> 6) & 63, ki = i & 63;
            int dh = (qi >> 3) - (ki >> 3) + 7;
            int dw = (qi & 7)  - (ki & 7)  + 7;
            g_bias[i] = table[(dh * 15 + dw) * NHh + h];
        }
        return;
    }

    // ---------------- layernorm ----------------
    const int lb      = blk0 - 1664;
    const bool isQ    = lb < 1024;
    const int blk     = isQ ? lb : lb - 1024;
    const float* x    = isQ ? q : kv;
    const float* gg   = isQ ? gq : gkv;
    const float* bt   = isQ ? bqln : bkvln;
    bf16* yh          = isQ ? qnt : kvnt;

    float* sx  = sm;                  // [512][33]
    float* ps  = sm + 512*33;         // [8][32]
    float* ps2 = ps + 256;            // [8][32]
    float* smu = ps2 + 256;           // [32]
    float* sin_ = smu + 32;           // [32]

    const int b   = blk >> 7;
    const int n0  = (blk & 127) * 32;
    const int t   = tid & 31;
    const int cp  = tid >> 5;

    const float* xb = x + (size_t)b*Cc*Nn + n0;
    float s = 0.f, s2 = 0.f;
#pragma unroll 8
    for (int it = 0; it < 64; it++) {
        int c = it*8 + cp;
        float v = xb[(size_t)c*Nn + t];
        sx[c*33 + t] = v;
        s += v;  s2 = fmaf(v, v, s2);
    }
    ps[cp*32 + t] = s;  ps2[cp*32 + t] = s2;
    __syncthreads();
    if (tid < 32) {
        float a = 0.f, a2 = 0.f;
#pragma unroll
        for (int k = 0; k < 8; k++) { a += ps[k*32 + tid]; a2 += ps2[k*32 + tid]; }
        float mu  = a * (1.f/Cc);
        float var = a2 * (1.f/Cc) - mu*mu;
        smu[tid]  = mu;
        sin_[tid] = rsqrtf(var + EPSf);
    }
    __syncthreads();

    const float mu = smu[t], inv = sin_[t];
    float* yfb = isQ ? (qn + (size_t)b*Cc*Nn + n0) : nullptr;
#pragma unroll 8
    for (int it = 0; it < 64; it++) {
        int c = it*8 + cp;
        float o = (sx[c*33 + t] - mu) * inv * gg[c] + bt[c];
        sx[c*33 + t] = o;
        if (isQ) yfb[(size_t)c*Nn + t] = o;
    }
    __syncthreads();

    {
        int tok = tid & 31, cb = (tid >> 5) * 64;
        union { uint4 qv[8]; unsigned u[32]; } buf;
#pragma unroll
        for (int i = 0; i < 32; i++) {
            float v0 = sx[(cb + 2*i    )*33 + tok];
            float v1 = sx[(cb + 2*i + 1)*33 + tok];
            buf.u[i] = packbf(v0, v1);
        }
        uint4* dst = (uint4*)(yh + ((size_t)b*Nn + n0 + tok)*Cc + cb);
#pragma unroll
        for (int i = 0; i < 8; i++) dst[i] = buf.qv[i];
    }
}

// ================= bf16 GEMM (NT): merged Q/K/V projections ==================
// BK=64, 3-stage cp.async, 8 stages. smem buffers [128][72] per operand.
__global__ __launch_bounds__(256, 2) void gemm_qkv_bf(const bf16* __restrict__ Aq,
                                                      const bf16* __restrict__ Akv,
                                                      const float* __restrict__ bq,
                                                      const float* __restrict__ bk,
                                                      const float* __restrict__ bv,
                                                      bf16* __restrict__ outQ,
                                                      bf16* __restrict__ outK,
                                                      bf16* __restrict__ outV)
{
    extern __shared__ __align__(16) bf16 smraw[];
    bf16* As = smraw;                 // 3 x 128*72
    bf16* Bs = smraw + 3*9216;        // 3 x 128*72

    const int seg = blockIdx.y >> 2;            // 0=Q 1=K 2=V
    const bf16*  A    = seg ? Akv : Aq;
    const bf16*  W    = g_Wh + (size_t)seg*Cc*Cc;
    const float* bias = (seg == 0) ? bq : (seg == 1) ? bk : bv;
    bf16*        out  = (seg == 0) ? outQ : (seg == 1) ? outK : outV;
    const bool   rope = (seg < 2);
    const int j0 = (blockIdx.y & 3) * 128;

    const int t0 = blockIdx.x * 128;
    const int b  = t0 >> 12;
    const int n0 = t0 & 4095;
    const int tid = threadIdx.x;
    const int lane = tid & 31, wid = tid >> 5;
    const int wm = wid & 1, wn = wid >> 1;
    const int r = lane >> 2, q = lane & 3;
    const int grp = lane >> 3, lr = lane & 7;

    float acc[4][4][4];
#pragma unroll
    for (int i = 0; i < 4; i++)
#pragma unroll
        for (int j = 0; j < 4; j++)
#pragma unroll
            for (int k = 0; k < 4; k++) acc[i][j][k] = 0.f;

#define LOAD_QKV(S, BUF)                                                        \
    {                                                                           \
        bf16* Ad = As + (BUF)*9216;                                             \
        bf16* Bd = Bs + (BUF)*9216;                                             \
        int c0 = (S)*64;                                                        \
        _Pragma("unroll")                                                       \
        for (int u = 0; u < 4; u++) {                                           \
            int flat = u*256 + tid;                                             \
            int m = flat >> 3, kc = flat & 7;                                   \
            CP16(sptr(Ad + m*72 + kc*8),                                        \
                 A + (size_t)(t0+m)*Cc + c0 + kc*8);                            \
            CP16(sptr(Bd + m*72 + kc*8),                                        \
                 W + (size_t)(j0+m)*Cc + c0 + kc*8);                            \
        }                                                                       \
    }

    LOAD_QKV(0, 0); CP_COMMIT();
    LOAD_QKV(1, 1); CP_COMMIT();

#pragma unroll 1
    for (int s = 0; s < 8; s++) {
        if (s < 7) { CP_WAIT(1); } else { CP_WAIT(0); }
        __syncthreads();
        if (s < 6) { LOAD_QKV(s+2, (s+2)%3); CP_COMMIT(); }

        const bf16* Ac = As + (s%3)*9216;
        const bf16* Bc = Bs + (s%3)*9216;
#pragma unroll
        for (int kk = 0; kk < 4; kk++) {
            unsigned af[4][4], bfr[4][2];
#pragma unroll
            for (int i = 0; i < 4; i++) {
                int m  = wm*64 + 16*i + ((grp & 1) ? 8 : 0) + lr;
                int ka = (grp & 2) ? 8 : 0;
                ldsm_x4(af[i][0], af[i][1], af[i][2], af[i][3],
                        sptr(Ac + m*72 + kk*16 + ka));
            }
#pragma unroll
            for (int jg = 0; jg < 2; jg++) {
                int n = wn*32 + jg*16 + ((grp & 2) ? 8 : 0) + lr;
                int ka = (grp & 1) ? 8 : 0;
                ldsm_x4(bfr[jg*2][0], bfr[jg*2][1], bfr[jg*2+1][0], bfr[jg*2+1][1],
                        sptr(Bc + n*72 + kk*16 + ka));
            }
#pragma unroll
            for (int i = 0; i < 4; i++)
#pragma unroll
                for (int j = 0; j < 4; j++)
                    mma_bf16(acc[i][j], af[i], bfr[j]);
        }
    }
#undef LOAD_QKV

    // ---- epilogue: bias (+ RoPE, fp32), store bf16 ----
#pragma unroll
    for (int i = 0; i < 4; i++) {
        int ntok = n0 + wm*64 + 16*i + r;
#pragma unroll
        for (int j = 0; j < 4; j++) {
            int jj = j0 + wn*32 + 8*j + 2*q;
            int hh = jj >> 6;
            int d  = jj & 63;                  // even
            float bv0 = bias[jj], bv1 = bias[jj+1];
#pragma unroll
            for (int half = 0; half < 2; half++) {
                int n = ntok + 8*half;
                float v0 = acc[i][j][2*half+0] + bv0;
                float v1 = acc[i][j][2*half+1] + bv1;
                float x, y;
                if (rope) {
                    int p = (n << 5) + (d >> 1);
                    float sv = g_sin[p], cv = g_cos[p];
                    x = v0*cv - v1*sv;
                    y = v0*sv + v1*cv;
                } else { x = v0; y = v1; }
                *(__nv_bfloat162*)&out[(((size_t)b*NHh + hh)*Nn + n)*Dd + d] =
                    __floats2bfloat162_rn(x, y);
            }
        }
    }
}

// ================= bf16 GEMM (NT): output projection, BK=64 ==================
__global__ __launch_bounds__(256, 2) void gemm_o_bf(const bf16* __restrict__ A,
                                                    const bf16* __restrict__ W,
                                                    const float* __restrict__ bias,
                                                    const float* __restrict__ resid,
                                                    float* __restrict__ out)
{
    extern __shared__ __align__(16) bf16 smraw[];
    bf16* As = smraw;                 // 3 x 128*72
    bf16* Bs = smraw + 3*9216;        // 3 x 128*72

    const int t0 = blockIdx.x * 128;
    const int b  = t0 >> 12;
    const int n0 = t0 & 4095;
    const int j0 = blockIdx.y * 128;
    const int tid = threadIdx.x;
    const int lane = tid & 31, wid = tid >> 5;
    const int wm = wid & 1, wn = wid >> 1;
    const int r = lane >> 2, q = lane & 3;
    const int grp = lane >> 3, lr = lane & 7;

    float acc[4][4][4];
#pragma unroll
    for (int i = 0; i < 4; i++)
#pragma unroll
        for (int j = 0; j < 4; j++)
#pragma unroll
            for (int k = 0; k < 4; k++) acc[i][j][k] = 0.f;

#define LOAD_O(S, BUF)                                                          \
    {                                                                           \
        bf16* Ad = As + (BUF)*9216;                                             \
        bf16* Bd = Bs + (BUF)*9216;                                             \
        int c0 = (S)*64;                                                        \
        _Pragma("unroll")                                                       \
        for (int u = 0; u < 4; u++) {                                           \
            int flat = u*256 + tid;                                             \
            int m = flat >> 3, kc = flat & 7;                                   \
            CP16(sptr(Ad + m*72 + kc*8),                                        \
                 A + (size_t)(t0+m)*Cc + c0 + kc*8);                            \
            CP16(sptr(Bd + m*72 + kc*8),                                        \
                 W + (size_t)(j0+m)*Cc + c0 + kc*8);                            \
        }                                                                       \
    }

    LOAD_O(0, 0); CP_COMMIT();
    LOAD_O(1, 1); CP_COMMIT();

#pragma unroll 1
    for (int s = 0; s < 8; s++) {
        if (s < 7) { CP_WAIT(1); } else { CP_WAIT(0); }
        __syncthreads();
        if (s < 6) { LOAD_O(s+2, (s+2)%3); CP_COMMIT(); }

        const bf16* Ac = As + (s%3)*9216;
        const bf16* Bc = Bs + (s%3)*9216;
#pragma unroll
        for (int kk = 0; kk < 4; kk++) {
            unsigned af[4][4], bfr[4][2];
#pragma unroll
            for (int i = 0; i < 4; i++) {
                int m  = wm*64 + 16*i + ((grp & 1) ? 8 : 0) + lr;
                int ka = (grp & 2) ? 8 : 0;
                ldsm_x4(af[i][0], af[i][1], af[i][2], af[i][3],
                        sptr(Ac + m*72 + kk*16 + ka));
            }
#pragma unroll
            for (int jg = 0; jg < 2; jg++) {
                int n = wn*32 + jg*16 + ((grp & 2) ? 8 : 0) + lr;
                int ka = (grp & 1) ? 8 : 0;
                ldsm_x4(bfr[jg*2][0], bfr[jg*2][1], bfr[jg*2+1][0], bfr[jg*2+1][1],
                        sptr(Bc + n*72 + kk*16 + ka));
            }
#pragma unroll
            for (int i = 0; i < 4; i++)
#pragma unroll
                for (int j = 0; j < 4; j++)
                    mma_bf16(acc[i][j], af[i], bfr[j]);
        }
    }
#undef LOAD_O

    // ---- epilogue: bias + residual (fp32), write (B,C,N) ----
#pragma unroll
    for (int j = 0; j < 4; j++) {
        int jj0 = j0 + wn*32 + 8*j + 2*q;
#pragma unroll
        for (int col = 0; col < 2; col++) {
            int jj = jj0 + col;
            float bj = bias[jj];
            size_t rowbase = ((size_t)b*Cc + jj)*Nn;
#pragma unroll
            for (int i = 0; i < 4; i++) {
#pragma unroll
                for (int half = 0; half < 2; half++) {
                    int n = n0 + wm*64 + 16*i + r + 8*half;
                    size_t o = rowbase + n;
                    out[o] = acc[i][j][2*half + col] + bj + resid[o];
                }
            }
        }
    }
}

// ---------------- windowed attention (bf16 mma), 1 block per (head, window) --
__global__ __launch_bounds__(128) void attn_bf()
{
    __shared__ __align__(16) bf16 Qs[64*72];
    __shared__ __align__(16) bf16 Ks[64*72];
    __shared__ __align__(16) bf16 Vs[64*72];

    const int bx  = blockIdx.x;     // 0..4095
    const int h   = bx >> 9;
    const int win = bx & 511;
    const int b   = win >> 6;
    const int w   = win & 63;
    const int wy  = w >> 3, wx = w & 7;
    const int tid = threadIdx.x;
    const int lane = tid & 31, wid = tid >> 5;
    const int grp = lane >> 3, lr = lane & 7;

    {
        int t  = tid & 63;
        int c2 = tid >> 6;
        int n_t = ((wy*8 + (t >> 3)) << 6) + wx*8 + (t & 7);
        size_t base = (((size_t)b*NHh + h)*Nn + n_t)*Dd;
#pragma unroll
        for (int u = 0; u < 4; u++) {
            int off = c2*32 + u*8;
            uint4 qv = *(const uint4*)((const char*)g_Qh + (base + off)*2);
            uint4 kv = *(const uint4*)((const char*)g_Kh + (base + off)*2);
            uint4 vv = *(const uint4*)((const char*)g_Vh + (base + off)*2);
            *(uint4*)((char*)Qs + (t*72 + off)*2) = qv;
            *(uint4*)((char*)Ks + (t*72 + off)*2) = kv;
            *(uint4*)((char*)Vs + (t*72 + off)*2) = vv;
        }
    }
    __syncthreads();

    const int m0 = wid * 16;

    unsigned af[4][4];
#pragma unroll
    for (int kk = 0; kk < 4; kk++) {
        int m  = m0 + ((grp & 1) ? 8 : 0) + lr;
        int ka = (grp & 2) ? 8 : 0;
        ldsm_x4(af[kk][0], af[kk][1], af[kk][2], af[kk][3],
                sptr(Qs + m*72 + kk*16 + ka));
    }

    float s[8][4];
#pragma unroll
    for (int j = 0; j < 8; j++)
#pragma unroll
        for (int c = 0; c < 4; c++) s[j][c] = 0.f;

#pragma unroll
    for (int kk = 0; kk < 4; kk++) {
        unsigned bfr[8][2];
#pragma unroll
        for (int jg = 0; jg < 4; jg++) {
            int n  = jg*16 + ((grp & 2) ? 8 : 0) + lr;
            int ka = (grp & 1) ? 8 : 0;
            ldsm_x4(bfr[jg*2][0], bfr[jg*2][1], bfr[jg*2+1][0], bfr[jg*2+1][1],
                    sptr(Ks + n*72 + kk*16 + ka));
        }
#pragma unroll
        for (int j = 0; j < 8; j++)
            mma_bf16(s[j], af[kk], bfr[j]);
    }

    const float* bh = g_bias + (h << 12);
    const int row0 = m0 + (lane >> 2);
    const int col0 = 2 * (lane & 3);
    float mx0 = -1e30f, mx1 = -1e30f;
#pragma unroll
    for (int j = 0; j < 8; j++) {
        float2 b0 = *(const float2*)(bh + row0*64 + 8*j + col0);
        float2 b1 = *(const float2*)(bh + (row0+8)*64 + 8*j + col0);
        s[j][0] = fmaf(s[j][0], 0.125f, b0.x);
        s[j][1] = fmaf(s[j][1], 0.125f, b0.y);
        s[j][2] = fmaf(s[j][2], 0.125f, b1.x);
        s[j][3] = fmaf(s[j][3], 0.125f, b1.y);
        mx0 = fmaxf(mx0, fmaxf(s[j][0], s[j][1]));
        mx1 = fmaxf(mx1, fmaxf(s[j][2], s[j][3]));
    }
    mx0 = fmaxf(mx0, __shfl_xor_sync(0xffffffffu, mx0, 1));
    mx0 = fmaxf(mx0, __shfl_xor_sync(0xffffffffu, mx0, 2));
    mx1 = fmaxf(mx1, __shfl_xor_sync(0xffffffffu, mx1, 1));
    mx1 = fmaxf(mx1, __shfl_xor_sync(0xffffffffu, mx1, 2));

    float sum0 = 0.f, sum1 = 0.f;
#pragma unroll
    for (int j = 0; j < 8; j++) {
        s[j][0] = __expf(s[j][0] - mx0);
        s[j][1] = __expf(s[j][1] - mx0);
        s[j][2] = __expf(s[j][2] - mx1);
        s[j][3] = __expf(s[j][3] - mx1);
        sum0 += s[j][0] + s[j][1];
        sum1 += s[j][2] + s[j][3];
    }
    sum0 += __shfl_xor_sync(0xffffffffu, sum0, 1);
    sum0 += __shfl_xor_sync(0xffffffffu, sum0, 2);
    sum1 += __shfl_xor_sync(0xffffffffu, sum1, 1);
    sum1 += __shfl_xor_sync(0xffffffffu, sum1, 2);
    float inv0 = 1.f / sum0, inv1 = 1.f / sum1;

    float o[8][4];
#pragma unroll
    for (int j = 0; j < 8; j++)
#pragma unroll
        for (int c = 0; c < 4; c++) o[j][c] = 0.f;

#pragma unroll
    for (int kk = 0; kk < 4; kk++) {
        unsigned pa[4];
        pa[0] = packbf(s[2*kk  ][0], s[2*kk  ][1]);
        pa[1] = packbf(s[2*kk  ][2], s[2*kk  ][3]);
        pa[2] = packbf(s[2*kk+1][0], s[2*kk+1][1]);
        pa[3] = packbf(s[2*kk+1][2], s[2*kk+1][3]);
        unsigned vb[8][2];
#pragma unroll
        for (int jg = 0; jg < 4; jg++) {
            int rowk = kk*16 + ((grp & 1) ? 8 : 0) + lr;
            int cold = jg*16 + ((grp & 2) ? 8 : 0);
            ldsm_x4t(vb[jg*2][0], vb[jg*2][1], vb[jg*2+1][0], vb[jg*2+1][1],
                     sptr(Vs + rowk*72 + cold));
        }
#pragma unroll
        for (int j = 0; j < 8; j++)
            mma_bf16(o[j], pa, vb[j]);
    }

    {
        int tA = row0, tB = row0 + 8;
        int nA = ((wy*8 + (tA >> 3)) << 6) + wx*8 + (tA & 7);
        int nB = ((wy*8 + (tB >> 3)) << 6) + wx*8 + (tB & 7);
        size_t baseA = ((size_t)b*Nn + nA)*Cc + (h << 6);
        size_t baseB = ((size_t)b*Nn + nB)*Cc + (h << 6);
#pragma unroll
        for (int j = 0; j < 8; j++) {
            int d = 8*j + col0;
            *(__nv_bfloat162*)&g_AOh[baseA + d] =
                __floats2bfloat162_rn(o[j][0]*inv0, o[j][1]*inv0);
            *(__nv_bfloat162*)&g_AOh[baseB + d] =
                __floats2bfloat162_rn(o[j][2]*inv1, o[j][3]*inv1);
        }
    }
}

// ---------------- host side ----------------
extern "C" void kernel_launch(void* const* d_in, const int* in_sizes, int n_in,
                              void* d_out, int out_size)
{
    const float* q    = (const float*)d_in[0];
    const float* kv   = (const float*)d_in[1];
    const float* gq   = (const float*)d_in[2];
    const float* bqln = (const float*)d_in[3];
    const float* gkv  = (const float*)d_in[4];
    const float* bkvln= (const float*)d_in[5];
    const float* Wq   = (const float*)d_in[6];
    const float* bq   = (const float*)d_in[7];
    const float* Wk   = (const float*)d_in[8];
    const float* bk   = (const float*)d_in[9];
    const float* Wv   = (const float*)d_in[10];
    const float* bv   = (const float*)d_in[11];
    const float* Wo   = (const float*)d_in[12];
    const float* bo   = (const float*)d_in[13];
    const float* tbl  = (const float*)d_in[14];
    float* out = (float*)d_out;

    void* p;
    cudaGetSymbolAddress(&p, g_qn);   float* qn   = (float*)p;
    cudaGetSymbolAddress(&p, g_qnt);  bf16* qnt   = (bf16*)p;
    cudaGetSymbolAddress(&p, g_kvnt); bf16* kvnt  = (bf16*)p;
    cudaGetSymbolAddress(&p, g_Wh);   bf16* Wh    = (bf16*)p;
    cudaGetSymbolAddress(&p, g_Qh);   bf16* Qb    = (bf16*)p;
    cudaGetSymbolAddress(&p, g_Kh);   bf16* Kb    = (bf16*)p;
    cudaGetSymbolAddress(&p, g_Vh);   bf16* Vb    = (bf16*)p;
    cudaGetSymbolAddress(&p, g_AOh);  bf16* AO    = (bf16*)p;

    const int SMEM_LN = (512*33 + 512 + 64) * 4;     // 69888 B
    const int SMEM_G  = (6*9216) * 2;                // 110592 B
    static int smem_set = 0;
    if (!smem_set) {
        cudaFuncSetAttribute(fused_pre,   cudaFuncAttributeMaxDynamicSharedMemorySize, SMEM_LN);
        cudaFuncSetAttribute(gemm_qkv_bf, cudaFuncAttributeMaxDynamicSharedMemorySize, SMEM_G);
        cudaFuncSetAttribute(gemm_o_bf,   cudaFuncAttributeMaxDynamicSharedMemorySize, SMEM_G);
        smem_set = 1;
    }

    // 0: fused prep + both layernorms (one launch)
    fused_pre<<<3712, 256, SMEM_LN>>>(q, kv, gq, bqln, gkv, bkvln,
                                      Wq, Wk, Wv, Wo, tbl, qn, qnt, kvnt);

    // 1: merged Q/K/V projections (rope fused for Q and K)
    gemm_qkv_bf<<<dim3(256, 12), 256, SMEM_G>>>(qnt, kvnt, bq, bk, bv, Qb, Kb, Vb);

    // 2: windowed attention
    attn_bf<<<NHh * Bb * 64, 128>>>();

    // 3: output projection + bias + residual -> (B,C,H,W)
    gemm_o_bf<<<dim3(256, 4), 256, SMEM_G>>>(AO, Wh + 3*Cc*Cc, bo, qn, out);
}

// round 13
// speedup vs baseline: 1.0865x; 1.0179x over previous
#include <cuda_runtime.h>
#include <cuda_bf16.h>
#include <math.h>

#define Bb   8
#define Cc   512
#define Nn   4096
#define NHh  8
#define Dd   64
#define EPSf 1e-5f

typedef __nv_bfloat16 bf16;

// ---------------- scratch (device globals; no allocation) ----------------
__device__ float g_qn  [Bb*Cc*Nn];        // layernormed q, (B,C,N) fp32 (residual)
__device__ bf16  g_qnt [Bb*Nn*Cc];        // layernormed q, token-major (B,N,C) bf16
__device__ bf16  g_kvnt[Bb*Nn*Cc];        // layernormed kv, token-major bf16
__device__ bf16  g_Wh  [4*Cc*Cc];         // Wq,Wk,Wv,Wo in bf16
__device__ bf16  g_Qh  [Bb*NHh*Nn*Dd];    // (B,NH,N,D) rope applied
__device__ bf16  g_Kh  [Bb*NHh*Nn*Dd];
__device__ bf16  g_Vh  [Bb*NHh*Nn*Dd];
__device__ bf16  g_AOh [Bb*Nn*Cc];        // attention out, (B,N,C)
__device__ float g_sin [Nn*32];
__device__ float g_cos [Nn*32];
__device__ float g_bias[NHh*64*64];       // (NH, Ws, Ws)

// ---------------- helpers ----------------
__device__ __forceinline__ unsigned sptr(const void* p) {
    return (unsigned)__cvta_generic_to_shared(p);
}
#define CP16(d, s)  asm volatile("cp.async.cg.shared.global [%0], [%1], 16;" :: "r"(d), "l"(s))
#define CP_COMMIT() asm volatile("cp.async.commit_group;")
#define CP_WAIT(n)  asm volatile("cp.async.wait_group %0;" :: "n"(n))

__device__ __forceinline__ void ldsm_x4(unsigned& r0, unsigned& r1, unsigned& r2, unsigned& r3, unsigned a) {
    asm volatile("ldmatrix.sync.aligned.m8n8.x4.shared.b16 {%0,%1,%2,%3}, [%4];"
                 : "=r"(r0), "=r"(r1), "=r"(r2), "=r"(r3) : "r"(a));
}
__device__ __forceinline__ void ldsm_x4t(unsigned& r0, unsigned& r1, unsigned& r2, unsigned& r3, unsigned a) {
    asm volatile("ldmatrix.sync.aligned.m8n8.x4.trans.shared.b16 {%0,%1,%2,%3}, [%4];"
                 : "=r"(r0), "=r"(r1), "=r"(r2), "=r"(r3) : "r"(a));
}
__device__ __forceinline__ void mma_bf16(float* c, const unsigned* a, const unsigned* b) {
    asm volatile(
        "mma.sync.aligned.m16n8k16.row.col.f32.bf16.bf16.f32 "
        "{%0,%1,%2,%3}, {%4,%5,%6,%7}, {%8,%9}, {%0,%1,%2,%3};"
        : "+f"(c[0]), "+f"(c[1]), "+f"(c[2]), "+f"(c[3])
        : "r"(a[0]), "r"(a[1]), "r"(a[2]), "r"(a[3]), "r"(b[0]), "r"(b[1]));
}
__device__ __forceinline__ unsigned packbf(float lo, float hi) {
    unsigned d; asm("cvt.rn.bf16x2.f32 %0, %1, %2;" : "=r"(d) : "f"(hi), "f"(lo)); return d;
}

// ============ prep: weight cvt + rope table + bias table (no smem) ==========
__global__ __launch_bounds__(256) void prep_kernel(const float* __restrict__ w0,
                                                   const float* __restrict__ w1,
                                                   const float* __restrict__ w2,
                                                   const float* __restrict__ w3,
                                                   const float* __restrict__ table)
{
    int blk = blockIdx.x;
    if (blk < 1024) {                        // wcvt
        int i = blk * 256 + threadIdx.x;
        g_Wh[0*Cc*Cc + i] = __float2bfloat16_rn(w0[i]);
        g_Wh[1*Cc*Cc + i] = __float2bfloat16_rn(w1[i]);
        g_Wh[2*Cc*Cc + i] = __float2bfloat16_rn(w2[i]);
        g_Wh[3*Cc*Cc + i] = __float2bfloat16_rn(w3[i]);
    } else if (blk < 1536) {                 // rope
        int i = (blk - 1024) * 256 + threadIdx.x;
        int n = i >> 5, k = i & 31;
        float invf = exp2f(-(float)k * (13.287712379549449f / 32.0f));
        float ang  = (float)n * invf;
        float sv, cv;  sincosf(ang, &sv, &cv);
        g_sin[i] = sv;  g_cos[i] = cv;
    } else {                                 // bias
        int i = (blk - 1536) * 256 + threadIdx.x;
        int h  = i >> 12;
        int qi = (i >> 6) & 63, ki = i & 63;
        int dh = (qi >> 3) - (ki >> 3) + 7;
        int dw = (qi & 7)  - (ki & 7)  + 7;
        g_bias[i] = table[(dh * 15 + dw) * NHh + h];
    }
}

// ====== layernorm (both inputs, one launch): blocks [0,1024)=q, [1024,2048)=kv
__global__ __launch_bounds__(256) void ln_both(const float* __restrict__ q,
                                               const float* __restrict__ kv,
                                               const float* __restrict__ gq,
                                               const float* __restrict__ bqln,
                                               const float* __restrict__ gkv,
                                               const float* __restrict__ bkvln,
                                               float* __restrict__ qn,
                                               bf16* __restrict__ qnt,
                                               bf16* __restrict__ kvnt)
{
    extern __shared__ float sm[];
    float* sx  = sm;                  // [512][33]
    float* ps  = sm + 512*33;         // [8][32]
    float* ps2 = ps + 256;            // [8][32]
    float* smu = ps2 + 256;           // [32]
    float* sin_ = smu + 32;           // [32]

    const int blk0 = blockIdx.x;
    const bool isQ = blk0 < 1024;
    const int blk  = isQ ? blk0 : blk0 - 1024;
    const float* x  = isQ ? q : kv;
    const float* gg = isQ ? gq : gkv;
    const float* bt = isQ ? bqln : bkvln;
    bf16* yh        = isQ ? qnt : kvnt;

    const int b   = blk >> 7;
    const int n0  = (blk & 127) * 32;
    const int tid = threadIdx.x;
    const int t   = tid & 31;
    const int cp  = tid >> 5;

    const float* xb = x + (size_t)b*Cc*Nn + n0;
    float s = 0.f, s2 = 0.f;
#pragma unroll 8
    for (int it = 0; it < 64; it++) {
        int c = it*8 + cp;
        float v = xb[(size_t)c*Nn + t];
        sx[c*33 + t] = v;
        s += v;  s2 = fmaf(v, v, s2);
    }
    ps[cp*32 + t] = s;  ps2[cp*32 + t] = s2;
    __syncthreads();
    if (tid < 32) {
        float a = 0.f, a2 = 0.f;
#pragma unroll
        for (int k = 0; k < 8; k++) { a += ps[k*32 + tid]; a2 += ps2[k*32 + tid]; }
        float mu  = a * (1.f/Cc);
        float var = a2 * (1.f/Cc) - mu*mu;
        smu[tid]  = mu;
        sin_[tid] = rsqrtf(var + EPSf);
    }
    __syncthreads();

    const float mu = smu[t], inv = sin_[t];
    float* yfb = isQ ? (qn + (size_t)b*Cc*Nn + n0) : nullptr;
#pragma unroll 8
    for (int it = 0; it < 64; it++) {
        int c = it*8 + cp;
        float o = (sx[c*33 + t] - mu) * inv * gg[c] + bt[c];
        sx[c*33 + t] = o;
        if (isQ) yfb[(size_t)c*Nn + t] = o;
    }
    __syncthreads();

    {
        int tok = tid & 31, cb = (tid >> 5) * 64;
        union { uint4 qv[8]; unsigned u[32]; } buf;
#pragma unroll
        for (int i = 0; i < 32; i++) {
            float v0 = sx[(cb + 2*i    )*33 + tok];
            float v1 = sx[(cb + 2*i + 1)*33 + tok];
            buf.u[i] = packbf(v0, v1);
        }
        uint4* dst = (uint4*)(yh + ((size_t)b*Nn + n0 + tok)*Cc + cb);
#pragma unroll
        for (int i = 0; i < 8; i++) dst[i] = buf.qv[i];
    }
}

// ================= bf16 GEMM (NT): merged Q/K/V projections ==================
// BK=64, 3-stage cp.async, 8 stages. smem buffers [128][72] per operand.
__global__ __launch_bounds__(256, 2) void gemm_qkv_bf(const bf16* __restrict__ Aq,
                                                      const bf16* __restrict__ Akv,
                                                      const float* __restrict__ bq,
                                                      const float* __restrict__ bk,
                                                      const float* __restrict__ bv,
                                                      bf16* __restrict__ outQ,
                                                      bf16* __restrict__ outK,
                                                      bf16* __restrict__ outV)
{
    extern __shared__ __align__(16) bf16 smraw[];
    bf16* As = smraw;                 // 3 x 128*72
    bf16* Bs = smraw + 3*9216;        // 3 x 128*72

    const int seg = blockIdx.y >> 2;            // 0=Q 1=K 2=V
    const bf16*  A    = seg ? Akv : Aq;
    const bf16*  W    = g_Wh + (size_t)seg*Cc*Cc;
    const float* bias = (seg == 0) ? bq : (seg == 1) ? bk : bv;
    bf16*        out  = (seg == 0) ? outQ : (seg == 1) ? outK : outV;
    const bool   rope = (seg < 2);
    const int j0 = (blockIdx.y & 3) * 128;

    const int t0 = blockIdx.x * 128;
    const int b  = t0 >> 12;
    const int n0 = t0 & 4095;
    const int tid = threadIdx.x;
    const int lane = tid & 31, wid = tid >> 5;
    const int wm = wid & 1, wn = wid >> 1;
    const int r = lane >> 2, q = lane & 3;
    const int grp = lane >> 3, lr = lane & 7;

    float acc[4][4][4];
#pragma unroll
    for (int i = 0; i < 4; i++)
#pragma unroll
        for (int j = 0; j < 4; j++)
#pragma unroll
            for (int k = 0; k < 4; k++) acc[i][j][k] = 0.f;

#define LOAD_QKV(S, BUF)                                                        \
    {                                                                           \
        bf16* Ad = As + (BUF)*9216;                                             \
        bf16* Bd = Bs + (BUF)*9216;                                             \
        int c0 = (S)*64;                                                        \
        _Pragma("unroll")                                                       \
        for (int u = 0; u < 4; u++) {                                           \
            int flat = u*256 + tid;                                             \
            int m = flat >> 3, kc = flat & 7;                                   \
            CP16(sptr(Ad + m*72 + kc*8),                                        \
                 A + (size_t)(t0+m)*Cc + c0 + kc*8);                            \
            CP16(sptr(Bd + m*72 + kc*8),                                        \
                 W + (size_t)(j0+m)*Cc + c0 + kc*8);                            \
        }                                                                       \
    }

    LOAD_QKV(0, 0); CP_COMMIT();
    LOAD_QKV(1, 1); CP_COMMIT();

#pragma unroll 1
    for (int s = 0; s < 8; s++) {
        if (s < 7) { CP_WAIT(1); } else { CP_WAIT(0); }
        __syncthreads();
        if (s < 6) { LOAD_QKV(s+2, (s+2)%3); CP_COMMIT(); }

        const bf16* Ac = As + (s%3)*9216;
        const bf16* Bc = Bs + (s%3)*9216;
#pragma unroll
        for (int kk = 0; kk < 4; kk++) {
            unsigned af[4][4], bfr[4][2];
#pragma unroll
            for (int i = 0; i < 4; i++) {
                int m  = wm*64 + 16*i + ((grp & 1) ? 8 : 0) + lr;
                int ka = (grp & 2) ? 8 : 0;
                ldsm_x4(af[i][0], af[i][1], af[i][2], af[i][3],
                        sptr(Ac + m*72 + kk*16 + ka));
            }
#pragma unroll
            for (int jg = 0; jg < 2; jg++) {
                int n = wn*32 + jg*16 + ((grp & 2) ? 8 : 0) + lr;
                int ka = (grp & 1) ? 8 : 0;
                ldsm_x4(bfr[jg*2][0], bfr[jg*2][1], bfr[jg*2+1][0], bfr[jg*2+1][1],
                        sptr(Bc + n*72 + kk*16 + ka));
            }
#pragma unroll
            for (int i = 0; i < 4; i++)
#pragma unroll
                for (int j = 0; j < 4; j++)
                    mma_bf16(acc[i][j], af[i], bfr[j]);
        }
    }
#undef LOAD_QKV

    // ---- epilogue: bias (+ RoPE, fp32), store bf16 ----
#pragma unroll
    for (int i = 0; i < 4; i++) {
        int ntok = n0 + wm*64 + 16*i + r;
#pragma unroll
        for (int j = 0; j < 4; j++) {
            int jj = j0 + wn*32 + 8*j + 2*q;
            int hh = jj >> 6;
            int d  = jj & 63;                  // even
            float bv0 = bias[jj], bv1 = bias[jj+1];
#pragma unroll
            for (int half = 0; half < 2; half++) {
                int n = ntok + 8*half;
                float v0 = acc[i][j][2*half+0] + bv0;
                float v1 = acc[i][j][2*half+1] + bv1;
                float x, y;
                if (rope) {
                    int p = (n << 5) + (d >> 1);
                    float sv = g_sin[p], cv = g_cos[p];
                    x = v0*cv - v1*sv;
                    y = v0*sv + v1*cv;
                } else { x = v0; y = v1; }
                *(__nv_bfloat162*)&out[(((size_t)b*NHh + hh)*Nn + n)*Dd + d] =
                    __floats2bfloat162_rn(x, y);
            }
        }
    }
}

// ================= bf16 GEMM (NT): output projection, BK=64 ==================
// Coalesced epilogue: acc staged through smem [128][132] fp32, then
// warp-per-16-rows float4 streaming of resid/out.
__global__ __launch_bounds__(256, 2) void gemm_o_bf(const bf16* __restrict__ A,
                                                    const bf16* __restrict__ W,
                                                    const float* __restrict__ bias,
                                                    const float* __restrict__ resid,
                                                    float* __restrict__ out)
{
    extern __shared__ __align__(16) bf16 smraw[];
    bf16* As = smraw;                 // 3 x 128*72
    bf16* Bs = smraw + 3*9216;        // 3 x 128*72

    const int t0 = blockIdx.x * 128;
    const int b  = t0 >> 12;
    const int n0 = t0 & 4095;
    const int j0 = blockIdx.y * 128;
    const int tid = threadIdx.x;
    const int lane = tid & 31, wid = tid >> 5;
    const int wm = wid & 1, wn = wid >> 1;
    const int r = lane >> 2, q = lane & 3;
    const int grp = lane >> 3, lr = lane & 7;

    float acc[4][4][4];
#pragma unroll
    for (int i = 0; i < 4; i++)
#pragma unroll
        for (int j = 0; j < 4; j++)
#pragma unroll
            for (int k = 0; k < 4; k++) acc[i][j][k] = 0.f;

#define LOAD_O(S, BUF)                                                          \
    {                                                                           \
        bf16* Ad = As + (BUF)*9216;                                             \
        bf16* Bd = Bs + (BUF)*9216;                                             \
        int c0 = (S)*64;                                                        \
        _Pragma("unroll")                                                       \
        for (int u = 0; u < 4; u++) {                                           \
            int flat = u*256 + tid;                                             \
            int m = flat >> 3, kc = flat & 7;                                   \
            CP16(sptr(Ad + m*72 + kc*8),                                        \
                 A + (size_t)(t0+m)*Cc + c0 + kc*8);                            \
            CP16(sptr(Bd + m*72 + kc*8),                                        \
                 W + (size_t)(j0+m)*Cc + c0 + kc*8);                            \
        }                                                                       \
    }

    LOAD_O(0, 0); CP_COMMIT();
    LOAD_O(1, 1); CP_COMMIT();

#pragma unroll 1
    for (int s = 0; s < 8; s++) {
        if (s < 7) { CP_WAIT(1); } else { CP_WAIT(0); }
        __syncthreads();
        if (s < 6) { LOAD_O(s+2, (s+2)%3); CP_COMMIT(); }

        const bf16* Ac = As + (s%3)*9216;
        const bf16* Bc = Bs + (s%3)*9216;
#pragma unroll
        for (int kk = 0; kk < 4; kk++) {
            unsigned af[4][4], bfr[4][2];
#pragma unroll
            for (int i = 0; i < 4; i++) {
                int m  = wm*64 + 16*i + ((grp & 1) ? 8 : 0) + lr;
                int ka = (grp & 2) ? 8 : 0;
                ldsm_x4(af[i][0], af[i][1], af[i][2], af[i][3],
                        sptr(Ac + m*72 + kk*16 + ka));
            }
#pragma unroll
            for (int jg = 0; jg < 2; jg++) {
                int n = wn*32 + jg*16 + ((grp & 2) ? 8 : 0) + lr;
                int ka = (grp & 1) ? 8 : 0;
                ldsm_x4(bfr[jg*2][0], bfr[jg*2][1], bfr[jg*2+1][0], bfr[jg*2+1][1],
                        sptr(Bc + n*72 + kk*16 + ka));
            }
#pragma unroll
            for (int i = 0; i < 4; i++)
#pragma unroll
                for (int j = 0; j < 4; j++)
                    mma_bf16(acc[i][j], af[i], bfr[j]);
        }
    }
#undef LOAD_O

    // ---- coalesced epilogue: stage acc in smem, then float4 stream ----
    __syncthreads();                       // all LDSM reads of last stage done
    float* sacc = (float*)smraw;           // [128][132] fp32 = 67584 B
#pragma unroll
    for (int i = 0; i < 4; i++) {
#pragma unroll
        for (int j = 0; j < 4; j++) {
#pragma unroll
            for (int half = 0; half < 2; half++) {
#pragma unroll
                for (int col = 0; col < 2; col++) {
                    int row = wn*32 + 8*j + 2*q + col;
                    int n   = wm*64 + 16*i + r + 8*half;
                    sacc[row*132 + n] = acc[i][j][2*half + col];
                }
            }
        }
    }
    __syncthreads();

    {
        int row0 = wid * 16;
#pragma unroll
        for (int rr = 0; rr < 16; rr++) {
            int row = row0 + rr;
            int jj  = j0 + row;
            float bj = bias[jj];
            int n = n0 + lane*4;
            size_t o = ((size_t)b*Cc + jj)*Nn + n;
            float4 v   = *(float4*)&sacc[row*132 + lane*4];
            float4 res = *(const float4*)&resid[o];
            v.x += bj + res.x;  v.y += bj + res.y;
            v.z += bj + res.z;  v.w += bj + res.w;
            *(float4*)&out[o] = v;
        }
    }
}

// ---------------- windowed attention (bf16 mma), 1 block per (head, window) --
__global__ __launch_bounds__(128) void attn_bf()
{
    __shared__ __align__(16) bf16 Qs[64*72];
    __shared__ __align__(16) bf16 Ks[64*72];
    __shared__ __align__(16) bf16 Vs[64*72];

    const int bx  = blockIdx.x;     // 0..4095
    const int h   = bx >> 9;
    const int win = bx & 511;
    const int b   = win >> 6;
    const int w   = win & 63;
    const int wy  = w >> 3, wx = w & 7;
    const int tid = threadIdx.x;
    const int lane = tid & 31, wid = tid >> 5;
    const int grp = lane >> 3, lr = lane & 7;

    {
        int t  = tid & 63;
        int c2 = tid >> 6;
        int n_t = ((wy*8 + (t >> 3)) << 6) + wx*8 + (t & 7);
        size_t base = (((size_t)b*NHh + h)*Nn + n_t)*Dd;
#pragma unroll
        for (int u = 0; u < 4; u++) {
            int off = c2*32 + u*8;
            uint4 qv = *(const uint4*)((const char*)g_Qh + (base + off)*2);
            uint4 kv = *(const uint4*)((const char*)g_Kh + (base + off)*2);
            uint4 vv = *(const uint4*)((const char*)g_Vh + (base + off)*2);
            *(uint4*)((char*)Qs + (t*72 + off)*2) = qv;
            *(uint4*)((char*)Ks + (t*72 + off)*2) = kv;
            *(uint4*)((char*)Vs + (t*72 + off)*2) = vv;
        }
    }
    __syncthreads();

    const int m0 = wid * 16;

    unsigned af[4][4];
#pragma unroll
    for (int kk = 0; kk < 4; kk++) {
        int m  = m0 + ((grp & 1) ? 8 : 0) + lr;
        int ka = (grp & 2) ? 8 : 0;
        ldsm_x4(af[kk][0], af[kk][1], af[kk][2], af[kk][3],
                sptr(Qs + m*72 + kk*16 + ka));
    }

    float s[8][4];
#pragma unroll
    for (int j = 0; j < 8; j++)
#pragma unroll
        for (int c = 0; c < 4; c++) s[j][c] = 0.f;

#pragma unroll
    for (int kk = 0; kk < 4; kk++) {
        unsigned bfr[8][2];
#pragma unroll
        for (int jg = 0; jg < 4; jg++) {
            int n  = jg*16 + ((grp & 2) ? 8 : 0) + lr;
            int ka = (grp & 1) ? 8 : 0;
            ldsm_x4(bfr[jg*2][0], bfr[jg*2][1], bfr[jg*2+1][0], bfr[jg*2+1][1],
                    sptr(Ks + n*72 + kk*16 + ka));
        }
#pragma unroll
        for (int j = 0; j < 8; j++)
            mma_bf16(s[j], af[kk], bfr[j]);
    }

    const float* bh = g_bias + (h << 12);
    const int row0 = m0 + (lane >> 2);
    const int col0 = 2 * (lane & 3);
    float mx0 = -1e30f, mx1 = -1e30f;
#pragma unroll
    for (int j = 0; j < 8; j++) {
        float2 b0 = *(const float2*)(bh + row0*64 + 8*j + col0);
        float2 b1 = *(const float2*)(bh + (row0+8)*64 + 8*j + col0);
        s[j][0] = fmaf(s[j][0], 0.125f, b0.x);
        s[j][1] = fmaf(s[j][1], 0.125f, b0.y);
        s[j][2] = fmaf(s[j][2], 0.125f, b1.x);
        s[j][3] = fmaf(s[j][3], 0.125f, b1.y);
        mx0 = fmaxf(mx0, fmaxf(s[j][0], s[j][1]));
        mx1 = fmaxf(mx1, fmaxf(s[j][2], s[j][3]));
    }
    mx0 = fmaxf(mx0, __shfl_xor_sync(0xffffffffu, mx0, 1));
    mx0 = fmaxf(mx0, __shfl_xor_sync(0xffffffffu, mx0, 2));
    mx1 = fmaxf(mx1, __shfl_xor_sync(0xffffffffu, mx1, 1));
    mx1 = fmaxf(mx1, __shfl_xor_sync(0xffffffffu, mx1, 2));

    float sum0 = 0.f, sum1 = 0.f;
#pragma unroll
    for (int j = 0; j < 8; j++) {
        s[j][0] = __expf(s[j][0] - mx0);
        s[j][1] = __expf(s[j][1] - mx0);
        s[j][2] = __expf(s[j][2] - mx1);
        s[j][3] = __expf(s[j][3] - mx1);
        sum0 += s[j][0] + s[j][1];
        sum1 += s[j][2] + s[j][3];
    }
    sum0 += __shfl_xor_sync(0xffffffffu, sum0, 1);
    sum0 += __shfl_xor_sync(0xffffffffu, sum0, 2);
    sum1 += __shfl_xor_sync(0xffffffffu, sum1, 1);
    sum1 += __shfl_xor_sync(0xffffffffu, sum1, 2);
    float inv0 = 1.f / sum0, inv1 = 1.f / sum1;

    float o[8][4];
#pragma unroll
    for (int j = 0; j < 8; j++)
#pragma unroll
        for (int c = 0; c < 4; c++) o[j][c] = 0.f;

#pragma unroll
    for (int kk = 0; kk < 4; kk++) {
        unsigned pa[4];
        pa[0] = packbf(s[2*kk  ][0], s[2*kk  ][1]);
        pa[1] = packbf(s[2*kk  ][2], s[2*kk  ][3]);
        pa[2] = packbf(s[2*kk+1][0], s[2*kk+1][1]);
        pa[3] = packbf(s[2*kk+1][2], s[2*kk+1][3]);
        unsigned vb[8][2];
#pragma unroll
        for (int jg = 0; jg < 4; jg++) {
            int rowk = kk*16 + ((grp & 1) ? 8 : 0) + lr;
            int cold = jg*16 + ((grp & 2) ? 8 : 0);
            ldsm_x4t(vb[jg*2][0], vb[jg*2][1], vb[jg*2+1][0], vb[jg*2+1][1],
                     sptr(Vs + rowk*72 + cold));
        }
#pragma unroll
        for (int j = 0; j < 8; j++)
            mma_bf16(o[j], pa, vb[j]);
    }

    {
        int tA = row0, tB = row0 + 8;
        int nA = ((wy*8 + (tA >> 3)) << 6) + wx*8 + (tA & 7);
        int nB = ((wy*8 + (tB >> 3)) << 6) + wx*8 + (tB & 7);
        size_t baseA = ((size_t)b*Nn + nA)*Cc + (h << 6);
        size_t baseB = ((size_t)b*Nn + nB)*Cc + (h << 6);
#pragma unroll
        for (int j = 0; j < 8; j++) {
            int d = 8*j + col0;
            *(__nv_bfloat162*)&g_AOh[baseA + d] =
                __floats2bfloat162_rn(o[j][0]*inv0, o[j][1]*inv0);
            *(__nv_bfloat162*)&g_AOh[baseB + d] =
                __floats2bfloat162_rn(o[j][2]*inv1, o[j][3]*inv1);
        }
    }
}

// ---------------- host side ----------------
extern "C" void kernel_launch(void* const* d_in, const int* in_sizes, int n_in,
                              void* d_out, int out_size)
{
    const float* q    = (const float*)d_in[0];
    const float* kv   = (const float*)d_in[1];
    const float* gq   = (const float*)d_in[2];
    const float* bqln = (const float*)d_in[3];
    const float* gkv  = (const float*)d_in[4];
    const float* bkvln= (const float*)d_in[5];
    const float* Wq   = (const float*)d_in[6];
    const float* bq   = (const float*)d_in[7];
    const float* Wk   = (const float*)d_in[8];
    const float* bk   = (const float*)d_in[9];
    const float* Wv   = (const float*)d_in[10];
    const float* bv   = (const float*)d_in[11];
    const float* Wo   = (const float*)d_in[12];
    const float* bo   = (const float*)d_in[13];
    const float* tbl  = (const float*)d_in[14];
    float* out = (float*)d_out;

    void* p;
    cudaGetSymbolAddress(&p, g_qn);   float* qn   = (float*)p;
    cudaGetSymbolAddress(&p, g_qnt);  bf16* qnt   = (bf16*)p;
    cudaGetSymbolAddress(&p, g_kvnt); bf16* kvnt  = (bf16*)p;
    cudaGetSymbolAddress(&p, g_Wh);   bf16* Wh    = (bf16*)p;
    cudaGetSymbolAddress(&p, g_Qh);   bf16* Qb    = (bf16*)p;
    cudaGetSymbolAddress(&p, g_Kh);   bf16* Kb    = (bf16*)p;
    cudaGetSymbolAddress(&p, g_Vh);   bf16* Vb    = (bf16*)p;
    cudaGetSymbolAddress(&p, g_AOh);  bf16* AO    = (bf16*)p;

    const int SMEM_LN = (512*33 + 512 + 64) * 4;     // 69888 B
    const int SMEM_G  = (6*9216) * 2;                // 110592 B
    static int smem_set = 0;
    if (!smem_set) {
        cudaFuncSetAttribute(ln_both,     cudaFuncAttributeMaxDynamicSharedMemorySize, SMEM_LN);
        cudaFuncSetAttribute(gemm_qkv_bf, cudaFuncAttributeMaxDynamicSharedMemorySize, SMEM_G);
        cudaFuncSetAttribute(gemm_o_bf,   cudaFuncAttributeMaxDynamicSharedMemorySize, SMEM_G);
        smem_set = 1;
    }

    // 0: weight cvt + rope + bias tables (tiny, no smem)
    prep_kernel<<<1664, 256>>>(Wq, Wk, Wv, Wo, tbl);

    // 1: both layernorms, one launch
    ln_both<<<2048, 256, SMEM_LN>>>(q, kv, gq, bqln, gkv, bkvln, qn, qnt, kvnt);

    // 2: merged Q/K/V projections (rope fused for Q and K)
    gemm_qkv_bf<<<dim3(256, 12), 256, SMEM_G>>>(qnt, kvnt, bq, bk, bv, Qb, Kb, Vb);

    // 3: windowed attention
    attn_bf<<<NHh * Bb * 64, 128>>>();

    // 4: output projection + bias + residual -> (B,C,H,W)
    gemm_o_bf<<<dim3(256, 4), 256, SMEM_G>>>(AO, Wh + 3*Cc*Cc, bo, qn, out);
}

// round 14
// speedup vs baseline: 1.1030x; 1.0152x over previous
#include <cuda_runtime.h>
#include <cuda_bf16.h>
#include <math.h>

#define Bb   8
#define Cc   512
#define Nn   4096
#define NHh  8
#define Dd   64
#define EPSf 1e-5f

typedef __nv_bfloat16 bf16;

// ---------------- scratch (device globals; no allocation) ----------------
__device__ float g_qn  [Bb*Cc*Nn];        // layernormed q, (B,C,N) fp32 (residual)
__device__ bf16  g_qnt [Bb*Nn*Cc];        // layernormed q, token-major (B,N,C) bf16
__device__ bf16  g_kvnt[Bb*Nn*Cc];        // layernormed kv, token-major bf16
__device__ bf16  g_Wh  [4*Cc*Cc];         // Wq,Wk,Wv,Wo in bf16
__device__ bf16  g_Qh  [Bb*NHh*Nn*Dd];    // (B,NH,N,D) rope applied
__device__ bf16  g_Kh  [Bb*NHh*Nn*Dd];
__device__ bf16  g_Vh  [Bb*NHh*Nn*Dd];
__device__ bf16  g_AOh [Bb*Nn*Cc];        // attention out, (B,N,C)
__device__ float g_sin [Nn*32];
__device__ float g_cos [Nn*32];
__device__ float g_bias[NHh*64*64];       // (NH, Ws, Ws)

// ---------------- helpers ----------------
__device__ __forceinline__ unsigned sptr(const void* p) {
    return (unsigned)__cvta_generic_to_shared(p);
}
#define CP16(d, s)  asm volatile("cp.async.cg.shared.global [%0], [%1], 16;" :: "r"(d), "l"(s))
#define CP_COMMIT() asm volatile("cp.async.commit_group;")
#define CP_WAIT(n)  asm volatile("cp.async.wait_group %0;" :: "n"(n))

__device__ __forceinline__ void ldsm_x4(unsigned& r0, unsigned& r1, unsigned& r2, unsigned& r3, unsigned a) {
    asm volatile("ldmatrix.sync.aligned.m8n8.x4.shared.b16 {%0,%1,%2,%3}, [%4];"
                 : "=r"(r0), "=r"(r1), "=r"(r2), "=r"(r3) : "r"(a));
}
__device__ __forceinline__ void ldsm_x4t(unsigned& r0, unsigned& r1, unsigned& r2, unsigned& r3, unsigned a) {
    asm volatile("ldmatrix.sync.aligned.m8n8.x4.trans.shared.b16 {%0,%1,%2,%3}, [%4];"
                 : "=r"(r0), "=r"(r1), "=r"(r2), "=r"(r3) : "r"(a));
}
__device__ __forceinline__ void mma_bf16(float* c, const unsigned* a, const unsigned* b) {
    asm volatile(
        "mma.sync.aligned.m16n8k16.row.col.f32.bf16.bf16.f32 "
        "{%0,%1,%2,%3}, {%4,%5,%6,%7}, {%8,%9}, {%0,%1,%2,%3};"
        : "+f"(c[0]), "+f"(c[1]), "+f"(c[2]), "+f"(c[3])
        : "r"(a[0]), "r"(a[1]), "r"(a[2]), "r"(a[3]), "r"(b[0]), "r"(b[1]));
}
__device__ __forceinline__ unsigned packbf(float lo, float hi) {
    unsigned d; asm("cvt.rn.bf16x2.f32 %0, %1, %2;" : "=r"(d) : "f"(hi), "f"(lo)); return d;
}

// ============ prep: weight cvt + rope table + bias table (no smem) ==========
__global__ __launch_bounds__(256) void prep_kernel(const float* __restrict__ w0,
                                                   const float* __restrict__ w1,
                                                   const float* __restrict__ w2,
                                                   const float* __restrict__ w3,
                                                   const float* __restrict__ table)
{
    int blk = blockIdx.x;
    if (blk < 1024) {                        // wcvt
        int i = blk * 256 + threadIdx.x;
        g_Wh[0*Cc*Cc + i] = __float2bfloat16_rn(w0[i]);
        g_Wh[1*Cc*Cc + i] = __float2bfloat16_rn(w1[i]);
        g_Wh[2*Cc*Cc + i] = __float2bfloat16_rn(w2[i]);
        g_Wh[3*Cc*Cc + i] = __float2bfloat16_rn(w3[i]);
    } else if (blk < 1536) {                 // rope
        int i = (blk - 1024) * 256 + threadIdx.x;
        int n = i >> 5, k = i & 31;
        float invf = exp2f(-(float)k * (13.287712379549449f / 32.0f));
        float ang  = (float)n * invf;
        float sv, cv;  sincosf(ang, &sv, &cv);
        g_sin[i] = sv;  g_cos[i] = cv;
    } else {                                 // bias
        int i = (blk - 1536) * 256 + threadIdx.x;
        int h  = i >> 12;
        int qi = (i >> 6) & 63, ki = i & 63;
        int dh = (qi >> 3) - (ki >> 3) + 7;
        int dw = (qi & 7)  - (ki & 7)  + 7;
        g_bias[i] = table[(dh * 15 + dw) * NHh + h];
    }
}

// ====== layernorm: 32 tokens x 512 C per block, smem transpose ======
template<bool F32OUT>
__global__ __launch_bounds__(256) void ln_kernel(const float* __restrict__ x,
                                                 const float* __restrict__ g,
                                                 const float* __restrict__ bt,
                                                 float* __restrict__ yf,
                                                 bf16* __restrict__ yh)
{
    extern __shared__ float sm[];
    float* sx  = sm;                  // [512][33]
    float* ps  = sm + 512*33;         // [8][32]
    float* ps2 = ps + 256;            // [8][32]
    float* smu = ps2 + 256;           // [32]
    float* sin_ = smu + 32;           // [32] inv

    const int blk = blockIdx.x;       // 0..1023
    const int b   = blk >> 7;
    const int n0  = (blk & 127) * 32;
    const int tid = threadIdx.x;
    const int t   = tid & 31;
    const int cp  = tid >> 5;

    const float* xb = x + (size_t)b*Cc*Nn + n0;
    float s = 0.f, s2 = 0.f;
#pragma unroll 8
    for (int it = 0; it < 64; it++) {
        int c = it*8 + cp;
        float v = xb[(size_t)c*Nn + t];
        sx[c*33 + t] = v;
        s += v;  s2 = fmaf(v, v, s2);
    }
    ps[cp*32 + t] = s;  ps2[cp*32 + t] = s2;
    __syncthreads();
    if (tid < 32) {
        float a = 0.f, a2 = 0.f;
#pragma unroll
        for (int k = 0; k < 8; k++) { a += ps[k*32 + tid]; a2 += ps2[k*32 + tid]; }
        float mu  = a * (1.f/Cc);
        float var = a2 * (1.f/Cc) - mu*mu;
        smu[tid]  = mu;
        sin_[tid] = rsqrtf(var + EPSf);
    }
    __syncthreads();

    const float mu = smu[t], inv = sin_[t];
    float* yfb = F32OUT ? (yf + (size_t)b*Cc*Nn + n0) : nullptr;
#pragma unroll 8
    for (int it = 0; it < 64; it++) {
        int c = it*8 + cp;
        float o = (sx[c*33 + t] - mu) * inv * g[c] + bt[c];
        sx[c*33 + t] = o;
        if (F32OUT) yfb[(size_t)c*Nn + t] = o;
    }
    __syncthreads();

    {
        int tok = tid & 31, cb = (tid >> 5) * 64;
        union { uint4 q[8]; unsigned u[32]; } buf;
#pragma unroll
        for (int i = 0; i < 32; i++) {
            float v0 = sx[(cb + 2*i    )*33 + tok];
            float v1 = sx[(cb + 2*i + 1)*33 + tok];
            buf.u[i] = packbf(v0, v1);
        }
        uint4* dst = (uint4*)(yh + ((size_t)b*Nn + n0 + tok)*Cc + cb);
#pragma unroll
        for (int i = 0; i < 8; i++) dst[i] = buf.q[i];
    }
}

// ================= bf16 GEMM (NT): merged Q/K/V projections ==================
// BK=64, 3-stage cp.async, 8 stages. smem buffers [128][72] per operand.
__global__ __launch_bounds__(256, 2) void gemm_qkv_bf(const bf16* __restrict__ Aq,
                                                      const bf16* __restrict__ Akv,
                                                      const float* __restrict__ bq,
                                                      const float* __restrict__ bk,
                                                      const float* __restrict__ bv,
                                                      bf16* __restrict__ outQ,
                                                      bf16* __restrict__ outK,
                                                      bf16* __restrict__ outV)
{
    extern __shared__ __align__(16) bf16 smraw[];
    bf16* As = smraw;                 // 3 x 128*72
    bf16* Bs = smraw + 3*9216;        // 3 x 128*72

    const int seg = blockIdx.y >> 2;            // 0=Q 1=K 2=V
    const bf16*  A    = seg ? Akv : Aq;
    const bf16*  W    = g_Wh + (size_t)seg*Cc*Cc;
    const float* bias = (seg == 0) ? bq : (seg == 1) ? bk : bv;
    bf16*        out  = (seg == 0) ? outQ : (seg == 1) ? outK : outV;
    const bool   rope = (seg < 2);
    const int j0 = (blockIdx.y & 3) * 128;

    const int t0 = blockIdx.x * 128;
    const int b  = t0 >> 12;
    const int n0 = t0 & 4095;
    const int tid = threadIdx.x;
    const int lane = tid & 31, wid = tid >> 5;
    const int wm = wid & 1, wn = wid >> 1;
    const int r = lane >> 2, q = lane & 3;
    const int grp = lane >> 3, lr = lane & 7;

    float acc[4][4][4];
#pragma unroll
    for (int i = 0; i < 4; i++)
#pragma unroll
        for (int j = 0; j < 4; j++)
#pragma unroll
            for (int k = 0; k < 4; k++) acc[i][j][k] = 0.f;

#define LOAD_QKV(S, BUF)                                                        \
    {                                                                           \
        bf16* Ad = As + (BUF)*9216;                                             \
        bf16* Bd = Bs + (BUF)*9216;                                             \
        int c0 = (S)*64;                                                        \
        _Pragma("unroll")                                                       \
        for (int u = 0; u < 4; u++) {                                           \
            int flat = u*256 + tid;                                             \
            int m = flat >> 3, kc = flat & 7;                                   \
            CP16(sptr(Ad + m*72 + kc*8),                                        \
                 A + (size_t)(t0+m)*Cc + c0 + kc*8);                            \
            CP16(sptr(Bd + m*72 + kc*8),                                        \
                 W + (size_t)(j0+m)*Cc + c0 + kc*8);                            \
        }                                                                       \
    }

    LOAD_QKV(0, 0); CP_COMMIT();
    LOAD_QKV(1, 1); CP_COMMIT();

#pragma unroll 1
    for (int s = 0; s < 8; s++) {
        if (s < 7) { CP_WAIT(1); } else { CP_WAIT(0); }
        __syncthreads();
        if (s < 6) { LOAD_QKV(s+2, (s+2)%3); CP_COMMIT(); }

        const bf16* Ac = As + (s%3)*9216;
        const bf16* Bc = Bs + (s%3)*9216;
#pragma unroll
        for (int kk = 0; kk < 4; kk++) {
            unsigned af[4][4], bfr[4][2];
#pragma unroll
            for (int i = 0; i < 4; i++) {
                int m  = wm*64 + 16*i + ((grp & 1) ? 8 : 0) + lr;
                int ka = (grp & 2) ? 8 : 0;
                ldsm_x4(af[i][0], af[i][1], af[i][2], af[i][3],
                        sptr(Ac + m*72 + kk*16 + ka));
            }
#pragma unroll
            for (int jg = 0; jg < 2; jg++) {
                int n = wn*32 + jg*16 + ((grp & 2) ? 8 : 0) + lr;
                int ka = (grp & 1) ? 8 : 0;
                ldsm_x4(bfr[jg*2][0], bfr[jg*2][1], bfr[jg*2+1][0], bfr[jg*2+1][1],
                        sptr(Bc + n*72 + kk*16 + ka));
            }
#pragma unroll
            for (int i = 0; i < 4; i++)
#pragma unroll
                for (int j = 0; j < 4; j++)
                    mma_bf16(acc[i][j], af[i], bfr[j]);
        }
    }
#undef LOAD_QKV

    // ---- epilogue: bias (+ RoPE, fp32), store bf16 ----
#pragma unroll
    for (int i = 0; i < 4; i++) {
        int ntok = n0 + wm*64 + 16*i + r;
#pragma unroll
        for (int j = 0; j < 4; j++) {
            int jj = j0 + wn*32 + 8*j + 2*q;
            int hh = jj >> 6;
            int d  = jj & 63;                  // even
            float bv0 = bias[jj], bv1 = bias[jj+1];
#pragma unroll
            for (int half = 0; half < 2; half++) {
                int n = ntok + 8*half;
                float v0 = acc[i][j][2*half+0] + bv0;
                float v1 = acc[i][j][2*half+1] + bv1;
                float x, y;
                if (rope) {
                    int p = (n << 5) + (d >> 1);
                    float sv = g_sin[p], cv = g_cos[p];
                    x = v0*cv - v1*sv;
                    y = v0*sv + v1*cv;
                } else { x = v0; y = v1; }
                *(__nv_bfloat162*)&out[(((size_t)b*NHh + hh)*Nn + n)*Dd + d] =
                    __floats2bfloat162_rn(x, y);
            }
        }
    }
}

// ================= bf16 GEMM (NT): output projection, BK=64 ==================
__global__ __launch_bounds__(256, 2) void gemm_o_bf(const bf16* __restrict__ A,
                                                    const bf16* __restrict__ W,
                                                    const float* __restrict__ bias,
                                                    const float* __restrict__ resid,
                                                    float* __restrict__ out)
{
    extern __shared__ __align__(16) bf16 smraw[];
    bf16* As = smraw;                 // 3 x 128*72
    bf16* Bs = smraw + 3*9216;        // 3 x 128*72

    const int t0 = blockIdx.x * 128;
    const int b  = t0 >> 12;
    const int n0 = t0 & 4095;
    const int j0 = blockIdx.y * 128;
    const int tid = threadIdx.x;
    const int lane = tid & 31, wid = tid >> 5;
    const int wm = wid & 1, wn = wid >> 1;
    const int r = lane >> 2, q = lane & 3;
    const int grp = lane >> 3, lr = lane & 7;

    float acc[4][4][4];
#pragma unroll
    for (int i = 0; i < 4; i++)
#pragma unroll
        for (int j = 0; j < 4; j++)
#pragma unroll
            for (int k = 0; k < 4; k++) acc[i][j][k] = 0.f;

#define LOAD_O(S, BUF)                                                          \
    {                                                                           \
        bf16* Ad = As + (BUF)*9216;                                             \
        bf16* Bd = Bs + (BUF)*9216;                                             \
        int c0 = (S)*64;                                                        \
        _Pragma("unroll")                                                       \
        for (int u = 0; u < 4; u++) {                                           \
            int flat = u*256 + tid;                                             \
            int m = flat >> 3, kc = flat & 7;                                   \
            CP16(sptr(Ad + m*72 + kc*8),                                        \
                 A + (size_t)(t0+m)*Cc + c0 + kc*8);                            \
            CP16(sptr(Bd + m*72 + kc*8),                                        \
                 W + (size_t)(j0+m)*Cc + c0 + kc*8);                            \
        }                                                                       \
    }

    LOAD_O(0, 0); CP_COMMIT();
    LOAD_O(1, 1); CP_COMMIT();

#pragma unroll 1
    for (int s = 0; s < 8; s++) {
        if (s < 7) { CP_WAIT(1); } else { CP_WAIT(0); }
        __syncthreads();
        if (s < 6) { LOAD_O(s+2, (s+2)%3); CP_COMMIT(); }

        const bf16* Ac = As + (s%3)*9216;
        const bf16* Bc = Bs + (s%3)*9216;
#pragma unroll
        for (int kk = 0; kk < 4; kk++) {
            unsigned af[4][4], bfr[4][2];
#pragma unroll
            for (int i = 0; i < 4; i++) {
                int m  = wm*64 + 16*i + ((grp & 1) ? 8 : 0) + lr;
                int ka = (grp & 2) ? 8 : 0;
                ldsm_x4(af[i][0], af[i][1], af[i][2], af[i][3],
                        sptr(Ac + m*72 + kk*16 + ka));
            }
#pragma unroll
            for (int jg = 0; jg < 2; jg++) {
                int n = wn*32 + jg*16 + ((grp & 2) ? 8 : 0) + lr;
                int ka = (grp & 1) ? 8 : 0;
                ldsm_x4(bfr[jg*2][0], bfr[jg*2][1], bfr[jg*2+1][0], bfr[jg*2+1][1],
                        sptr(Bc + n*72 + kk*16 + ka));
            }
#pragma unroll
            for (int i = 0; i < 4; i++)
#pragma unroll
                for (int j = 0; j < 4; j++)
                    mma_bf16(acc[i][j], af[i], bfr[j]);
        }
    }
#undef LOAD_O

    // ---- epilogue: bias + residual (fp32), write (B,C,N) ----
#pragma unroll
    for (int j = 0; j < 4; j++) {
        int jj0 = j0 + wn*32 + 8*j + 2*q;
#pragma unroll
        for (int col = 0; col < 2; col++) {
            int jj = jj0 + col;
            float bj = bias[jj];
            size_t rowbase = ((size_t)b*Cc + jj)*Nn;
#pragma unroll
            for (int i = 0; i < 4; i++) {
#pragma unroll
                for (int half = 0; half < 2; half++) {
                    int n = n0 + wm*64 + 16*i + r + 8*half;
                    size_t o = rowbase + n;
                    out[o] = acc[i][j][2*half + col] + bj + resid[o];
                }
            }
        }
    }
}

// ---------------- windowed attention: 64 threads (2 warps), 1 window --------
// Each warp computes 32 Q rows -> K/V smem re-read halves vs 4-warp version.
__global__ __launch_bounds__(64) void attn_bf()
{
    __shared__ __align__(16) bf16 Qs[64*72];
    __shared__ __align__(16) bf16 Ks[64*72];
    __shared__ __align__(16) bf16 Vs[64*72];

    const int bx  = blockIdx.x;     // 0..4095
    const int h   = bx >> 9;
    const int win = bx & 511;
    const int b   = win >> 6;
    const int w   = win & 63;
    const int wy  = w >> 3, wx = w & 7;
    const int tid = threadIdx.x;
    const int lane = tid & 31, wid = tid >> 5;   // wid in {0,1}
    const int grp = lane >> 3, lr = lane & 7;

    // ---- load Q/K/V tiles (64 tokens x 64 d); thread = token ----
    {
        int t = tid;                 // 0..63
        int n_t = ((wy*8 + (t >> 3)) << 6) + wx*8 + (t & 7);
        size_t base = (((size_t)b*NHh + h)*Nn + n_t)*Dd;
#pragma unroll
        for (int u = 0; u < 8; u++) {
            int off = u*8;
            uint4 qv = *(const uint4*)((const char*)g_Qh + (base + off)*2);
            uint4 kv = *(const uint4*)((const char*)g_Kh + (base + off)*2);
            uint4 vv = *(const uint4*)((const char*)g_Vh + (base + off)*2);
            *(uint4*)((char*)Qs + (t*72 + off)*2) = qv;
            *(uint4*)((char*)Ks + (t*72 + off)*2) = kv;
            *(uint4*)((char*)Vs + (t*72 + off)*2) = vv;
        }
    }
    __syncthreads();

    const int m0 = wid * 32;

    // ---- Q fragments: 2 m16-tiles x 4 k-tiles ----
    unsigned af[2][4][4];
#pragma unroll
    for (int mi = 0; mi < 2; mi++)
#pragma unroll
        for (int kk = 0; kk < 4; kk++) {
            int m  = m0 + mi*16 + ((grp & 1) ? 8 : 0) + lr;
            int ka = (grp & 2) ? 8 : 0;
            ldsm_x4(af[mi][kk][0], af[mi][kk][1], af[mi][kk][2], af[mi][kk][3],
                    sptr(Qs + m*72 + kk*16 + ka));
        }

    // ---- S = Q K^T : 32 rows x 64 cols per warp ----
    float s[2][8][4];
#pragma unroll
    for (int mi = 0; mi < 2; mi++)
#pragma unroll
        for (int j = 0; j < 8; j++)
#pragma unroll
            for (int c = 0; c < 4; c++) s[mi][j][c] = 0.f;

#pragma unroll
    for (int kk = 0; kk < 4; kk++) {
        unsigned bfr[8][2];
#pragma unroll
        for (int jg = 0; jg < 4; jg++) {
            int n  = jg*16 + ((grp & 2) ? 8 : 0) + lr;
            int ka = (grp & 1) ? 8 : 0;
            ldsm_x4(bfr[jg*2][0], bfr[jg*2][1], bfr[jg*2+1][0], bfr[jg*2+1][1],
                    sptr(Ks + n*72 + kk*16 + ka));
        }
#pragma unroll
        for (int mi = 0; mi < 2; mi++)
#pragma unroll
            for (int j = 0; j < 8; j++)
                mma_bf16(s[mi][j], af[mi][kk], bfr[j]);
    }

    // ---- scale + bias + softmax (per 16-row group) ----
    const float* bh = g_bias + (h << 12);
    const int col0 = 2 * (lane & 3);
    float inv0[2], inv1[2];
#pragma unroll
    for (int mi = 0; mi < 2; mi++) {
        int row0 = m0 + mi*16 + (lane >> 2);
        float mx0 = -1e30f, mx1 = -1e30f;
#pragma unroll
        for (int j = 0; j < 8; j++) {
            float2 b0 = *(const float2*)(bh + row0*64 + 8*j + col0);
            float2 b1 = *(const float2*)(bh + (row0+8)*64 + 8*j + col0);
            s[mi][j][0] = fmaf(s[mi][j][0], 0.125f, b0.x);
            s[mi][j][1] = fmaf(s[mi][j][1], 0.125f, b0.y);
            s[mi][j][2] = fmaf(s[mi][j][2], 0.125f, b1.x);
            s[mi][j][3] = fmaf(s[mi][j][3], 0.125f, b1.y);
            mx0 = fmaxf(mx0, fmaxf(s[mi][j][0], s[mi][j][1]));
            mx1 = fmaxf(mx1, fmaxf(s[mi][j][2], s[mi][j][3]));
        }
        mx0 = fmaxf(mx0, __shfl_xor_sync(0xffffffffu, mx0, 1));
        mx0 = fmaxf(mx0, __shfl_xor_sync(0xffffffffu, mx0, 2));
        mx1 = fmaxf(mx1, __shfl_xor_sync(0xffffffffu, mx1, 1));
        mx1 = fmaxf(mx1, __shfl_xor_sync(0xffffffffu, mx1, 2));

        float sum0 = 0.f, sum1 = 0.f;
#pragma unroll
        for (int j = 0; j < 8; j++) {
            s[mi][j][0] = __expf(s[mi][j][0] - mx0);
            s[mi][j][1] = __expf(s[mi][j][1] - mx0);
            s[mi][j][2] = __expf(s[mi][j][2] - mx1);
            s[mi][j][3] = __expf(s[mi][j][3] - mx1);
            sum0 += s[mi][j][0] + s[mi][j][1];
            sum1 += s[mi][j][2] + s[mi][j][3];
        }
        sum0 += __shfl_xor_sync(0xffffffffu, sum0, 1);
        sum0 += __shfl_xor_sync(0xffffffffu, sum0, 2);
        sum1 += __shfl_xor_sync(0xffffffffu, sum1, 1);
        sum1 += __shfl_xor_sync(0xffffffffu, sum1, 2);
        inv0[mi] = 1.f / sum0;
        inv1[mi] = 1.f / sum1;
    }

    // ---- O = P V ----
    float o[2][8][4];
#pragma unroll
    for (int mi = 0; mi < 2; mi++)
#pragma unroll
        for (int j = 0; j < 8; j++)
#pragma unroll
            for (int c = 0; c < 4; c++) o[mi][j][c] = 0.f;

#pragma unroll
    for (int kk = 0; kk < 4; kk++) {
        unsigned vb[8][2];
#pragma unroll
        for (int jg = 0; jg < 4; jg++) {
            int rowk = kk*16 + ((grp & 1) ? 8 : 0) + lr;
            int cold = jg*16 + ((grp & 2) ? 8 : 0);
            ldsm_x4t(vb[jg*2][0], vb[jg*2][1], vb[jg*2+1][0], vb[jg*2+1][1],
                     sptr(Vs + rowk*72 + cold));
        }
#pragma unroll
        for (int mi = 0; mi < 2; mi++) {
            unsigned pa[4];
            pa[0] = packbf(s[mi][2*kk  ][0], s[mi][2*kk  ][1]);
            pa[1] = packbf(s[mi][2*kk  ][2], s[mi][2*kk  ][3]);
            pa[2] = packbf(s[mi][2*kk+1][0], s[mi][2*kk+1][1]);
            pa[3] = packbf(s[mi][2*kk+1][2], s[mi][2*kk+1][3]);
#pragma unroll
            for (int j = 0; j < 8; j++)
                mma_bf16(o[mi][j], pa, vb[j]);
        }
    }

    // ---- store to g_AOh (B,N,C) bf16 ----
#pragma unroll
    for (int mi = 0; mi < 2; mi++) {
        int row0 = m0 + mi*16 + (lane >> 2);
        int tA = row0, tB = row0 + 8;
        int nA = ((wy*8 + (tA >> 3)) << 6) + wx*8 + (tA & 7);
        int nB = ((wy*8 + (tB >> 3)) << 6) + wx*8 + (tB & 7);
        size_t baseA = ((size_t)b*Nn + nA)*Cc + (h << 6);
        size_t baseB = ((size_t)b*Nn + nB)*Cc + (h << 6);
#pragma unroll
        for (int j = 0; j < 8; j++) {
            int d = 8*j + col0;
            *(__nv_bfloat162*)&g_AOh[baseA + d] =
                __floats2bfloat162_rn(o[mi][j][0]*inv0[mi], o[mi][j][1]*inv0[mi]);
            *(__nv_bfloat162*)&g_AOh[baseB + d] =
                __floats2bfloat162_rn(o[mi][j][2]*inv1[mi], o[mi][j][3]*inv1[mi]);
        }
    }
}

// ---------------- host side ----------------
extern "C" void kernel_launch(void* const* d_in, const int* in_sizes, int n_in,
                              void* d_out, int out_size)
{
    const float* q    = (const float*)d_in[0];
    const float* kv   = (const float*)d_in[1];
    const float* gq   = (const float*)d_in[2];
    const float* bqln = (const float*)d_in[3];
    const float* gkv  = (const float*)d_in[4];
    const float* bkvln= (const float*)d_in[5];
    const float* Wq   = (const float*)d_in[6];
    const float* bq   = (const float*)d_in[7];
    const float* Wk   = (const float*)d_in[8];
    const float* bk   = (const float*)d_in[9];
    const float* Wv   = (const float*)d_in[10];
    const float* bv   = (const float*)d_in[11];
    const float* Wo   = (const float*)d_in[12];
    const float* bo   = (const float*)d_in[13];
    const float* tbl  = (const float*)d_in[14];
    float* out = (float*)d_out;

    void* p;
    cudaGetSymbolAddress(&p, g_qn);   float* qn   = (float*)p;
    cudaGetSymbolAddress(&p, g_qnt);  bf16* qnt   = (bf16*)p;
    cudaGetSymbolAddress(&p, g_kvnt); bf16* kvnt  = (bf16*)p;
    cudaGetSymbolAddress(&p, g_Wh);   bf16* Wh    = (bf16*)p;
    cudaGetSymbolAddress(&p, g_Qh);   bf16* Qb    = (bf16*)p;
    cudaGetSymbolAddress(&p, g_Kh);   bf16* Kb    = (bf16*)p;
    cudaGetSymbolAddress(&p, g_Vh);   bf16* Vb    = (bf16*)p;
    cudaGetSymbolAddress(&p, g_AOh);  bf16* AO    = (bf16*)p;

    const int SMEM_LN = (512*33 + 512 + 64) * 4;     // 69888 B
    const int SMEM_G  = (6*9216) * 2;                // 110592 B
    static int smem_set = 0;
    if (!smem_set) {
        cudaFuncSetAttribute(ln_kernel<true>,  cudaFuncAttributeMaxDynamicSharedMemorySize, SMEM_LN);
        cudaFuncSetAttribute(ln_kernel<false>, cudaFuncAttributeMaxDynamicSharedMemorySize, SMEM_LN);
        cudaFuncSetAttribute(gemm_qkv_bf,      cudaFuncAttributeMaxDynamicSharedMemorySize, SMEM_G);
        cudaFuncSetAttribute(gemm_o_bf,        cudaFuncAttributeMaxDynamicSharedMemorySize, SMEM_G);
        smem_set = 1;
    }

    // 0: weight cvt + rope + bias tables (tiny, no smem)
    prep_kernel<<<1664, 256>>>(Wq, Wk, Wv, Wo, tbl);

    // 1,2: layernorms (token-major bf16 out; q also fp32 channel-major)
    ln_kernel<true ><<<1024, 256, SMEM_LN>>>(q,  gq,  bqln,  qn, qnt);
    ln_kernel<false><<<1024, 256, SMEM_LN>>>(kv, gkv, bkvln, qn, kvnt);

    // 3: merged Q/K/V projections (rope fused for Q and K)
    gemm_qkv_bf<<<dim3(256, 12), 256, SMEM_G>>>(qnt, kvnt, bq, bk, bv, Qb, Kb, Vb);

    // 4: windowed attention (2 warps per window)
    attn_bf<<<NHh * Bb * 64, 64>>>();

    // 5: output projection + bias + residual -> (B,C,H,W)
    gemm_o_bf<<<dim3(256, 4), 256, SMEM_G>>>(AO, Wh + 3*Cc*Cc, bo, qn, out);
}

// round 15
// speedup vs baseline: 1.1481x; 1.0409x over previous
#include <cuda_runtime.h>
#include <cuda_bf16.h>
#include <math.h>

#define Bb   8
#define Cc   512
#define Nn   4096
#define NHh  8
#define Dd   64
#define EPSf 1e-5f

typedef __nv_bfloat16 bf16;

// ---------------- scratch (device globals; no allocation) ----------------
__device__ float g_qn  [Bb*Cc*Nn];        // layernormed q, (B,C,N) fp32 (residual)
__device__ bf16  g_qnt [Bb*Nn*Cc];        // layernormed q, token-major (B,N,C) bf16
__device__ bf16  g_kvnt[Bb*Nn*Cc];        // layernormed kv, token-major bf16
__device__ bf16  g_Wh  [4*Cc*Cc];         // Wq,Wk,Wv,Wo in bf16
__device__ bf16  g_Qh  [Bb*NHh*Nn*Dd];    // (B,NH,N,D) rope applied
__device__ bf16  g_Kh  [Bb*NHh*Nn*Dd];
__device__ bf16  g_Vh  [Bb*NHh*Nn*Dd];
__device__ bf16  g_AOh [Bb*Nn*Cc];        // attention out, (B,N,C)
__device__ float g_sin [Nn*32];
__device__ float g_cos [Nn*32];
__device__ float g_bias[NHh*64*64];       // (NH, Ws, Ws)

// ---------------- helpers ----------------
__device__ __forceinline__ unsigned sptr(const void* p) {
    return (unsigned)__cvta_generic_to_shared(p);
}
#define CP16(d, s)  asm volatile("cp.async.cg.shared.global [%0], [%1], 16;" :: "r"(d), "l"(s))
#define CP_COMMIT() asm volatile("cp.async.commit_group;")
#define CP_WAIT(n)  asm volatile("cp.async.wait_group %0;" :: "n"(n))

__device__ __forceinline__ void ldsm_x4(unsigned& r0, unsigned& r1, unsigned& r2, unsigned& r3, unsigned a) {
    asm volatile("ldmatrix.sync.aligned.m8n8.x4.shared.b16 {%0,%1,%2,%3}, [%4];"
                 : "=r"(r0), "=r"(r1), "=r"(r2), "=r"(r3) : "r"(a));
}
__device__ __forceinline__ void ldsm_x4t(unsigned& r0, unsigned& r1, unsigned& r2, unsigned& r3, unsigned a) {
    asm volatile("ldmatrix.sync.aligned.m8n8.x4.trans.shared.b16 {%0,%1,%2,%3}, [%4];"
                 : "=r"(r0), "=r"(r1), "=r"(r2), "=r"(r3) : "r"(a));
}
__device__ __forceinline__ void mma_bf16(float* c, const unsigned* a, const unsigned* b) {
    asm volatile(
        "mma.sync.aligned.m16n8k16.row.col.f32.bf16.bf16.f32 "
        "{%0,%1,%2,%3}, {%4,%5,%6,%7}, {%8,%9}, {%0,%1,%2,%3};"
        : "+f"(c[0]), "+f"(c[1]), "+f"(c[2]), "+f"(c[3])
        : "r"(a[0]), "r"(a[1]), "r"(a[2]), "r"(a[3]), "r"(b[0]), "r"(b[1]));
}
__device__ __forceinline__ unsigned packbf(float lo, float hi) {
    unsigned d; asm("cvt.rn.bf16x2.f32 %0, %1, %2;" : "=r"(d) : "f"(hi), "f"(lo)); return d;
}

// ============ prep: weight cvt + rope table + bias table (no smem) ==========
__global__ __launch_bounds__(256) void prep_kernel(const float* __restrict__ w0,
                                                   const float* __restrict__ w1,
                                                   const float* __restrict__ w2,
                                                   const float* __restrict__ w3,
                                                   const float* __restrict__ table)
{
    int blk = blockIdx.x;
    if (blk < 1024) {                        // wcvt
        int i = blk * 256 + threadIdx.x;
        g_Wh[0*Cc*Cc + i] = __float2bfloat16_rn(w0[i]);
        g_Wh[1*Cc*Cc + i] = __float2bfloat16_rn(w1[i]);
        g_Wh[2*Cc*Cc + i] = __float2bfloat16_rn(w2[i]);
        g_Wh[3*Cc*Cc + i] = __float2bfloat16_rn(w3[i]);
    } else if (blk < 1536) {                 // rope
        int i = (blk - 1024) * 256 + threadIdx.x;
        int n = i >> 5, k = i & 31;
        float invf = exp2f(-(float)k * (13.287712379549449f / 32.0f));
        float ang  = (float)n * invf;
        float sv, cv;  sincosf(ang, &sv, &cv);
        g_sin[i] = sv;  g_cos[i] = cv;
    } else {                                 // bias
        int i = (blk - 1536) * 256 + threadIdx.x;
        int h  = i >> 12;
        int qi = (i >> 6) & 63, ki = i & 63;
        int dh = (qi >> 3) - (ki >> 3) + 7;
        int dw = (qi & 7)  - (ki & 7)  + 7;
        g_bias[i] = table[(dh * 15 + dw) * NHh + h];
    }
}

// ====== layernorm: 32 tokens x 512 C per block, smem transpose ======
template<bool F32OUT>
__global__ __launch_bounds__(256) void ln_kernel(const float* __restrict__ x,
                                                 const float* __restrict__ g,
                                                 const float* __restrict__ bt,
                                                 float* __restrict__ yf,
                                                 bf16* __restrict__ yh)
{
    extern __shared__ float sm[];
    float* sx  = sm;                  // [512][33]
    float* ps  = sm + 512*33;         // [8][32]
    float* ps2 = ps + 256;            // [8][32]
    float* smu = ps2 + 256;           // [32]
    float* sin_ = smu + 32;           // [32] inv

    const int blk = blockIdx.x;       // 0..1023
    const int b   = blk >> 7;
    const int n0  = (blk & 127) * 32;
    const int tid = threadIdx.x;
    const int t   = tid & 31;
    const int cp  = tid >> 5;

    const float* xb = x + (size_t)b*Cc*Nn + n0;
    float s = 0.f, s2 = 0.f;
#pragma unroll 8
    for (int it = 0; it < 64; it++) {
        int c = it*8 + cp;
        float v = xb[(size_t)c*Nn + t];
        sx[c*33 + t] = v;
        s += v;  s2 = fmaf(v, v, s2);
    }
    ps[cp*32 + t] = s;  ps2[cp*32 + t] = s2;
    __syncthreads();
    if (tid < 32) {
        float a = 0.f, a2 = 0.f;
#pragma unroll
        for (int k = 0; k < 8; k++) { a += ps[k*32 + tid]; a2 += ps2[k*32 + tid]; }
        float mu  = a * (1.f/Cc);
        float var = a2 * (1.f/Cc) - mu*mu;
        smu[tid]  = mu;
        sin_[tid] = rsqrtf(var + EPSf);
    }
    __syncthreads();

    const float mu = smu[t], inv = sin_[t];
    float* yfb = F32OUT ? (yf + (size_t)b*Cc*Nn + n0) : nullptr;
#pragma unroll 8
    for (int it = 0; it < 64; it++) {
        int c = it*8 + cp;
        float o = (sx[c*33 + t] - mu) * inv * g[c] + bt[c];
        sx[c*33 + t] = o;
        if (F32OUT) yfb[(size_t)c*Nn + t] = o;
    }
    __syncthreads();

    {
        int tok = tid & 31, cb = (tid >> 5) * 64;
        union { uint4 q[8]; unsigned u[32]; } buf;
#pragma unroll
        for (int i = 0; i < 32; i++) {
            float v0 = sx[(cb + 2*i    )*33 + tok];
            float v1 = sx[(cb + 2*i + 1)*33 + tok];
            buf.u[i] = packbf(v0, v1);
        }
        uint4* dst = (uint4*)(yh + ((size_t)b*Nn + n0 + tok)*Cc + cb);
#pragma unroll
        for (int i = 0; i < 8; i++) dst[i] = buf.q[i];
    }
}

// ================= bf16 GEMM (NT): merged Q/K/V projections ==================
// BK=64, 3-stage cp.async, 8 stages. smem buffers [128][72] per operand.
// grid (12, 256): x = seg/j0 (fast -> A-tile L2 reuse), y = t0.
__global__ __launch_bounds__(256, 2) void gemm_qkv_bf(const bf16* __restrict__ Aq,
                                                      const bf16* __restrict__ Akv,
                                                      const float* __restrict__ bq,
                                                      const float* __restrict__ bk,
                                                      const float* __restrict__ bv,
                                                      bf16* __restrict__ outQ,
                                                      bf16* __restrict__ outK,
                                                      bf16* __restrict__ outV)
{
    extern __shared__ __align__(16) bf16 smraw[];
    bf16* As = smraw;                 // 3 x 128*72
    bf16* Bs = smraw + 3*9216;        // 3 x 128*72

    const int yy  = blockIdx.x;                 // 0..11
    const int seg = yy >> 2;                    // 0=Q 1=K 2=V
    const bf16*  A    = seg ? Akv : Aq;
    const bf16*  W    = g_Wh + (size_t)seg*Cc*Cc;
    const float* bias = (seg == 0) ? bq : (seg == 1) ? bk : bv;
    bf16*        out  = (seg == 0) ? outQ : (seg == 1) ? outK : outV;
    const bool   rope = (seg < 2);
    const int j0 = (yy & 3) * 128;

    const int t0 = blockIdx.y * 128;
    const int b  = t0 >> 12;
    const int n0 = t0 & 4095;
    const int tid = threadIdx.x;
    const int lane = tid & 31, wid = tid >> 5;
    const int wm = wid & 1, wn = wid >> 1;
    const int r = lane >> 2, q = lane & 3;
    const int grp = lane >> 3, lr = lane & 7;

    float acc[4][4][4];
#pragma unroll
    for (int i = 0; i < 4; i++)
#pragma unroll
        for (int j = 0; j < 4; j++)
#pragma unroll
            for (int k = 0; k < 4; k++) acc[i][j][k] = 0.f;

#define LOAD_QKV(S, BUF)                                                        \
    {                                                                           \
        bf16* Ad = As + (BUF)*9216;                                             \
        bf16* Bd = Bs + (BUF)*9216;                                             \
        int c0 = (S)*64;                                                        \
        _Pragma("unroll")                                                       \
        for (int u = 0; u < 4; u++) {                                           \
            int flat = u*256 + tid;                                             \
            int m = flat >> 3, kc = flat & 7;                                   \
            CP16(sptr(Ad + m*72 + kc*8),                                        \
                 A + (size_t)(t0+m)*Cc + c0 + kc*8);                            \
            CP16(sptr(Bd + m*72 + kc*8),                                        \
                 W + (size_t)(j0+m)*Cc + c0 + kc*8);                            \
        }                                                                       \
    }

    LOAD_QKV(0, 0); CP_COMMIT();
    LOAD_QKV(1, 1); CP_COMMIT();

#pragma unroll 1
    for (int s = 0; s < 8; s++) {
        if (s < 7) { CP_WAIT(1); } else { CP_WAIT(0); }
        __syncthreads();
        if (s < 6) { LOAD_QKV(s+2, (s+2)%3); CP_COMMIT(); }

        const bf16* Ac = As + (s%3)*9216;
        const bf16* Bc = Bs + (s%3)*9216;
#pragma unroll
        for (int kk = 0; kk < 4; kk++) {
            unsigned af[4][4], bfr[4][2];
#pragma unroll
            for (int i = 0; i < 4; i++) {
                int m  = wm*64 + 16*i + ((grp & 1) ? 8 : 0) + lr;
                int ka = (grp & 2) ? 8 : 0;
                ldsm_x4(af[i][0], af[i][1], af[i][2], af[i][3],
                        sptr(Ac + m*72 + kk*16 + ka));
            }
#pragma unroll
            for (int jg = 0; jg < 2; jg++) {
                int n = wn*32 + jg*16 + ((grp & 2) ? 8 : 0) + lr;
                int ka = (grp & 1) ? 8 : 0;
                ldsm_x4(bfr[jg*2][0], bfr[jg*2][1], bfr[jg*2+1][0], bfr[jg*2+1][1],
                        sptr(Bc + n*72 + kk*16 + ka));
            }
#pragma unroll
            for (int i = 0; i < 4; i++)
#pragma unroll
                for (int j = 0; j < 4; j++)
                    mma_bf16(acc[i][j], af[i], bfr[j]);
        }
    }
#undef LOAD_QKV

    // ---- epilogue: bias (+ RoPE, fp32), store bf16 ----
#pragma unroll
    for (int i = 0; i < 4; i++) {
        int ntok = n0 + wm*64 + 16*i + r;
#pragma unroll
        for (int j = 0; j < 4; j++) {
            int jj = j0 + wn*32 + 8*j + 2*q;
            int hh = jj >> 6;
            int d  = jj & 63;                  // even
            float bv0 = bias[jj], bv1 = bias[jj+1];
#pragma unroll
            for (int half = 0; half < 2; half++) {
                int n = ntok + 8*half;
                float v0 = acc[i][j][2*half+0] + bv0;
                float v1 = acc[i][j][2*half+1] + bv1;
                float x, y;
                if (rope) {
                    int p = (n << 5) + (d >> 1);
                    float sv = g_sin[p], cv = g_cos[p];
                    x = v0*cv - v1*sv;
                    y = v0*sv + v1*cv;
                } else { x = v0; y = v1; }
                *(__nv_bfloat162*)&out[(((size_t)b*NHh + hh)*Nn + n)*Dd + d] =
                    __floats2bfloat162_rn(x, y);
            }
        }
    }
}

// ================= bf16 GEMM (NT): output projection, BK=64 ==================
// grid (4, 256): x = j0 (fast -> A-tile L2 reuse), y = t0.
__global__ __launch_bounds__(256, 2) void gemm_o_bf(const bf16* __restrict__ A,
                                                    const bf16* __restrict__ W,
                                                    const float* __restrict__ bias,
                                                    const float* __restrict__ resid,
                                                    float* __restrict__ out)
{
    extern __shared__ __align__(16) bf16 smraw[];
    bf16* As = smraw;                 // 3 x 128*72
    bf16* Bs = smraw + 3*9216;        // 3 x 128*72

    const int t0 = blockIdx.y * 128;
    const int b  = t0 >> 12;
    const int n0 = t0 & 4095;
    const int j0 = blockIdx.x * 128;
    const int tid = threadIdx.x;
    const int lane = tid & 31, wid = tid >> 5;
    const int wm = wid & 1, wn = wid >> 1;
    const int r = lane >> 2, q = lane & 3;
    const int grp = lane >> 3, lr = lane & 7;

    float acc[4][4][4];
#pragma unroll
    for (int i = 0; i < 4; i++)
#pragma unroll
        for (int j = 0; j < 4; j++)
#pragma unroll
            for (int k = 0; k < 4; k++) acc[i][j][k] = 0.f;

#define LOAD_O(S, BUF)                                                          \
    {                                                                           \
        bf16* Ad = As + (BUF)*9216;                                             \
        bf16* Bd = Bs + (BUF)*9216;                                             \
        int c0 = (S)*64;                                                        \
        _Pragma("unroll")                                                       \
        for (int u = 0; u < 4; u++) {                                           \
            int flat = u*256 + tid;                                             \
            int m = flat >> 3, kc = flat & 7;                                   \
            CP16(sptr(Ad + m*72 + kc*8),                                        \
                 A + (size_t)(t0+m)*Cc + c0 + kc*8);                            \
            CP16(sptr(Bd + m*72 + kc*8),                                        \
                 W + (size_t)(j0+m)*Cc + c0 + kc*8);                            \
        }                                                                       \
    }

    LOAD_O(0, 0); CP_COMMIT();
    LOAD_O(1, 1); CP_COMMIT();

#pragma unroll 1
    for (int s = 0; s < 8; s++) {
        if (s < 7) { CP_WAIT(1); } else { CP_WAIT(0); }
        __syncthreads();
        if (s < 6) { LOAD_O(s+2, (s+2)%3); CP_COMMIT(); }

        const bf16* Ac = As + (s%3)*9216;
        const bf16* Bc = Bs + (s%3)*9216;
#pragma unroll
        for (int kk = 0; kk < 4; kk++) {
            unsigned af[4][4], bfr[4][2];
#pragma unroll
            for (int i = 0; i < 4; i++) {
                int m  = wm*64 + 16*i + ((grp & 1) ? 8 : 0) + lr;
                int ka = (grp & 2) ? 8 : 0;
                ldsm_x4(af[i][0], af[i][1], af[i][2], af[i][3],
                        sptr(Ac + m*72 + kk*16 + ka));
            }
#pragma unroll
            for (int jg = 0; jg < 2; jg++) {
                int n = wn*32 + jg*16 + ((grp & 2) ? 8 : 0) + lr;
                int ka = (grp & 1) ? 8 : 0;
                ldsm_x4(bfr[jg*2][0], bfr[jg*2][1], bfr[jg*2+1][0], bfr[jg*2+1][1],
                        sptr(Bc + n*72 + kk*16 + ka));
            }
#pragma unroll
            for (int i = 0; i < 4; i++)
#pragma unroll
                for (int j = 0; j < 4; j++)
                    mma_bf16(acc[i][j], af[i], bfr[j]);
        }
    }
#undef LOAD_O

    // ---- epilogue: bias + residual (fp32), write (B,C,N) ----
#pragma unroll
    for (int j = 0; j < 4; j++) {
        int jj0 = j0 + wn*32 + 8*j + 2*q;
#pragma unroll
        for (int col = 0; col < 2; col++) {
            int jj = jj0 + col;
            float bj = bias[jj];
            size_t rowbase = ((size_t)b*Cc + jj)*Nn;
#pragma unroll
            for (int i = 0; i < 4; i++) {
#pragma unroll
                for (int half = 0; half < 2; half++) {
                    int n = n0 + wm*64 + 16*i + r + 8*half;
                    size_t o = rowbase + n;
                    out[o] = acc[i][j][2*half + col] + bj + resid[o];
                }
            }
        }
    }
}

// ---------------- windowed attention (bf16 mma), 1 block per (head, window) --
// 4 warps; inputs staged with cp.async (no LDG->STS register round trip).
__global__ __launch_bounds__(128) void attn_bf()
{
    __shared__ __align__(16) bf16 Qs[64*72];
    __shared__ __align__(16) bf16 Ks[64*72];
    __shared__ __align__(16) bf16 Vs[64*72];

    const int bx  = blockIdx.x;     // 0..4095
    const int h   = bx >> 9;
    const int win = bx & 511;
    const int b   = win >> 6;
    const int w   = win & 63;
    const int wy  = w >> 3, wx = w & 7;
    const int tid = threadIdx.x;
    const int lane = tid & 31, wid = tid >> 5;
    const int grp = lane >> 3, lr = lane & 7;

    {
        int t  = tid & 63;
        int c2 = tid >> 6;
        int n_t = ((wy*8 + (t >> 3)) << 6) + wx*8 + (t & 7);
        size_t base = (((size_t)b*NHh + h)*Nn + n_t)*Dd;
#pragma unroll
        for (int u = 0; u < 4; u++) {
            int off = c2*32 + u*8;
            CP16(sptr((char*)Qs + (t*72 + off)*2), g_Qh + base + off);
            CP16(sptr((char*)Ks + (t*72 + off)*2), g_Kh + base + off);
            CP16(sptr((char*)Vs + (t*72 + off)*2), g_Vh + base + off);
        }
        CP_COMMIT();
        CP_WAIT(0);
    }
    __syncthreads();

    const int m0 = wid * 16;

    unsigned af[4][4];
#pragma unroll
    for (int kk = 0; kk < 4; kk++) {
        int m  = m0 + ((grp & 1) ? 8 : 0) + lr;
        int ka = (grp & 2) ? 8 : 0;
        ldsm_x4(af[kk][0], af[kk][1], af[kk][2], af[kk][3],
                sptr(Qs + m*72 + kk*16 + ka));
    }

    float s[8][4];
#pragma unroll
    for (int j = 0; j < 8; j++)
#pragma unroll
        for (int c = 0; c < 4; c++) s[j][c] = 0.f;

#pragma unroll
    for (int kk = 0; kk < 4; kk++) {
        unsigned bfr[8][2];
#pragma unroll
        for (int jg = 0; jg < 4; jg++) {
            int n  = jg*16 + ((grp & 2) ? 8 : 0) + lr;
            int ka = (grp & 1) ? 8 : 0;
            ldsm_x4(bfr[jg*2][0], bfr[jg*2][1], bfr[jg*2+1][0], bfr[jg*2+1][1],
                    sptr(Ks + n*72 + kk*16 + ka));
        }
#pragma unroll
        for (int j = 0; j < 8; j++)
            mma_bf16(s[j], af[kk], bfr[j]);
    }

    const float* bh = g_bias + (h << 12);
    const int row0 = m0 + (lane >> 2);
    const int col0 = 2 * (lane & 3);
    float mx0 = -1e30f, mx1 = -1e30f;
#pragma unroll
    for (int j = 0; j < 8; j++) {
        float2 b0 = *(const float2*)(bh + row0*64 + 8*j + col0);
        float2 b1 = *(const float2*)(bh + (row0+8)*64 + 8*j + col0);
        s[j][0] = fmaf(s[j][0], 0.125f, b0.x);
        s[j][1] = fmaf(s[j][1], 0.125f, b0.y);
        s[j][2] = fmaf(s[j][2], 0.125f, b1.x);
        s[j][3] = fmaf(s[j][3], 0.125f, b1.y);
        mx0 = fmaxf(mx0, fmaxf(s[j][0], s[j][1]));
        mx1 = fmaxf(mx1, fmaxf(s[j][2], s[j][3]));
    }
    mx0 = fmaxf(mx0, __shfl_xor_sync(0xffffffffu, mx0, 1));
    mx0 = fmaxf(mx0, __shfl_xor_sync(0xffffffffu, mx0, 2));
    mx1 = fmaxf(mx1, __shfl_xor_sync(0xffffffffu, mx1, 1));
    mx1 = fmaxf(mx1, __shfl_xor_sync(0xffffffffu, mx1, 2));

    float sum0 = 0.f, sum1 = 0.f;
#pragma unroll
    for (int j = 0; j < 8; j++) {
        s[j][0] = __expf(s[j][0] - mx0);
        s[j][1] = __expf(s[j][1] - mx0);
        s[j][2] = __expf(s[j][2] - mx1);
        s[j][3] = __expf(s[j][3] - mx1);
        sum0 += s[j][0] + s[j][1];
        sum1 += s[j][2] + s[j][3];
    }
    sum0 += __shfl_xor_sync(0xffffffffu, sum0, 1);
    sum0 += __shfl_xor_sync(0xffffffffu, sum0, 2);
    sum1 += __shfl_xor_sync(0xffffffffu, sum1, 1);
    sum1 += __shfl_xor_sync(0xffffffffu, sum1, 2);
    float inv0 = 1.f / sum0, inv1 = 1.f / sum1;

    float o[8][4];
#pragma unroll
    for (int j = 0; j < 8; j++)
#pragma unroll
        for (int c = 0; c < 4; c++) o[j][c] = 0.f;

#pragma unroll
    for (int kk = 0; kk < 4; kk++) {
        unsigned pa[4];
        pa[0] = packbf(s[2*kk  ][0], s[2*kk  ][1]);
        pa[1] = packbf(s[2*kk  ][2], s[2*kk  ][3]);
        pa[2] = packbf(s[2*kk+1][0], s[2*kk+1][1]);
        pa[3] = packbf(s[2*kk+1][2], s[2*kk+1][3]);
        unsigned vb[8][2];
#pragma unroll
        for (int jg = 0; jg < 4; jg++) {
            int rowk = kk*16 + ((grp & 1) ? 8 : 0) + lr;
            int cold = jg*16 + ((grp & 2) ? 8 : 0);
            ldsm_x4t(vb[jg*2][0], vb[jg*2][1], vb[jg*2+1][0], vb[jg*2+1][1],
                     sptr(Vs + rowk*72 + cold));
        }
#pragma unroll
        for (int j = 0; j < 8; j++)
            mma_bf16(o[j], pa, vb[j]);
    }

    {
        int tA = row0, tB = row0 + 8;
        int nA = ((wy*8 + (tA >> 3)) << 6) + wx*8 + (tA & 7);
        int nB = ((wy*8 + (tB >> 3)) << 6) + wx*8 + (tB & 7);
        size_t baseA = ((size_t)b*Nn + nA)*Cc + (h << 6);
        size_t baseB = ((size_t)b*Nn + nB)*Cc + (h << 6);
#pragma unroll
        for (int j = 0; j < 8; j++) {
            int d = 8*j + col0;
            *(__nv_bfloat162*)&g_AOh[baseA + d] =
                __floats2bfloat162_rn(o[j][0]*inv0, o[j][1]*inv0);
            *(__nv_bfloat162*)&g_AOh[baseB + d] =
                __floats2bfloat162_rn(o[j][2]*inv1, o[j][3]*inv1);
        }
    }
}

// ---------------- host side ----------------
extern "C" void kernel_launch(void* const* d_in, const int* in_sizes, int n_in,
                              void* d_out, int out_size)
{
    const float* q    = (const float*)d_in[0];
    const float* kv   = (const float*)d_in[1];
    const float* gq   = (const float*)d_in[2];
    const float* bqln = (const float*)d_in[3];
    const float* gkv  = (const float*)d_in[4];
    const float* bkvln= (const float*)d_in[5];
    const float* Wq   = (const float*)d_in[6];
    const float* bq   = (const float*)d_in[7];
    const float* Wk   = (const float*)d_in[8];
    const float* bk   = (const float*)d_in[9];
    const float* Wv   = (const float*)d_in[10];
    const float* bv   = (const float*)d_in[11];
    const float* Wo   = (const float*)d_in[12];
    const float* bo   = (const float*)d_in[13];
    const float* tbl  = (const float*)d_in[14];
    float* out = (float*)d_out;

    void* p;
    cudaGetSymbolAddress(&p, g_qn);   float* qn   = (float*)p;
    cudaGetSymbolAddress(&p, g_qnt);  bf16* qnt   = (bf16*)p;
    cudaGetSymbolAddress(&p, g_kvnt); bf16* kvnt  = (bf16*)p;
    cudaGetSymbolAddress(&p, g_Wh);   bf16* Wh    = (bf16*)p;
    cudaGetSymbolAddress(&p, g_Qh);   bf16* Qb    = (bf16*)p;
    cudaGetSymbolAddress(&p, g_Kh);   bf16* Kb    = (bf16*)p;
    cudaGetSymbolAddress(&p, g_Vh);   bf16* Vb    = (bf16*)p;
    cudaGetSymbolAddress(&p, g_AOh);  bf16* AO    = (bf16*)p;

    const int SMEM_LN = (512*33 + 512 + 64) * 4;     // 69888 B
    const int SMEM_G  = (6*9216) * 2;                // 110592 B
    static int smem_set = 0;
    if (!smem_set) {
        cudaFuncSetAttribute(ln_kernel<true>,  cudaFuncAttributeMaxDynamicSharedMemorySize, SMEM_LN);
        cudaFuncSetAttribute(ln_kernel<false>, cudaFuncAttributeMaxDynamicSharedMemorySize, SMEM_LN);
        cudaFuncSetAttribute(gemm_qkv_bf,      cudaFuncAttributeMaxDynamicSharedMemorySize, SMEM_G);
        cudaFuncSetAttribute(gemm_o_bf,        cudaFuncAttributeMaxDynamicSharedMemorySize, SMEM_G);
        smem_set = 1;
    }

    // 0: weight cvt + rope + bias tables (tiny, no smem)
    prep_kernel<<<1664, 256>>>(Wq, Wk, Wv, Wo, tbl);

    // 1,2: layernorms (token-major bf16 out; q also fp32 channel-major)
    ln_kernel<true ><<<1024, 256, SMEM_LN>>>(q,  gq,  bqln,  qn, qnt);
    ln_kernel<false><<<1024, 256, SMEM_LN>>>(kv, gkv, bkvln, qn, kvnt);

    // 3: merged Q/K/V projections (rope fused for Q and K); x fast = A reuse
    gemm_qkv_bf<<<dim3(12, 256), 256, SMEM_G>>>(qnt, kvnt, bq, bk, bv, Qb, Kb, Vb);

    // 4: windowed attention (4 warps, cp.async staging)
    attn_bf<<<NHh * Bb * 64, 128>>>();

    // 5: output projection + bias + residual -> (B,C,H,W)
    gemm_o_bf<<<dim3(4, 256), 256, SMEM_G>>>(AO, Wh + 3*Cc*Cc, bo, qn, out);
}

// round 16
// speedup vs baseline: 1.1537x; 1.0049x over previous
#include <cuda_runtime.h>
#include <cuda_bf16.h>
#include <math.h>

#define Bb   8
#define Cc   512
#define Nn   4096
#define NHh  8
#define Dd   64
#define EPSf 1e-5f

typedef __nv_bfloat16 bf16;

// ---------------- scratch (device globals; no allocation) ----------------
__device__ float g_qn  [Bb*Cc*Nn];        // layernormed q, (B,C,N) fp32 (residual)
__device__ bf16  g_qnt [Bb*Nn*Cc];        // layernormed q, token-major (B,N,C) bf16
__device__ bf16  g_kvnt[Bb*Nn*Cc];        // layernormed kv, token-major bf16
__device__ bf16  g_Wh  [4*Cc*Cc];         // Wq,Wk,Wv,Wo in bf16
__device__ bf16  g_Qh  [Bb*NHh*Nn*Dd];    // (B,NH,N,D) rope applied
__device__ bf16  g_Kh  [Bb*NHh*Nn*Dd];
__device__ bf16  g_Vh  [Bb*NHh*Nn*Dd];
__device__ bf16  g_AOh [Bb*Nn*Cc];        // attention out, (B,N,C)
__device__ float g_sin [Nn*32];
__device__ float g_cos [Nn*32];
__device__ float g_bias[NHh*64*64];       // (NH, Ws, Ws)

// ---------------- helpers ----------------
__device__ __forceinline__ unsigned sptr(const void* p) {
    return (unsigned)__cvta_generic_to_shared(p);
}
#define CP16(d, s)  asm volatile("cp.async.cg.shared.global [%0], [%1], 16;" :: "r"(d), "l"(s))
#define CP_COMMIT() asm volatile("cp.async.commit_group;")
#define CP_WAIT(n)  asm volatile("cp.async.wait_group %0;" :: "n"(n))

__device__ __forceinline__ void ldsm_x4(unsigned& r0, unsigned& r1, unsigned& r2, unsigned& r3, unsigned a) {
    asm volatile("ldmatrix.sync.aligned.m8n8.x4.shared.b16 {%0,%1,%2,%3}, [%4];"
                 : "=r"(r0), "=r"(r1), "=r"(r2), "=r"(r3) : "r"(a));
}
__device__ __forceinline__ void ldsm_x4t(unsigned& r0, unsigned& r1, unsigned& r2, unsigned& r3, unsigned a) {
    asm volatile("ldmatrix.sync.aligned.m8n8.x4.trans.shared.b16 {%0,%1,%2,%3}, [%4];"
                 : "=r"(r0), "=r"(r1), "=r"(r2), "=r"(r3) : "r"(a));
}
__device__ __forceinline__ void mma_bf16(float* c, const unsigned* a, const unsigned* b) {
    asm volatile(
        "mma.sync.aligned.m16n8k16.row.col.f32.bf16.bf16.f32 "
        "{%0,%1,%2,%3}, {%4,%5,%6,%7}, {%8,%9}, {%0,%1,%2,%3};"
        : "+f"(c[0]), "+f"(c[1]), "+f"(c[2]), "+f"(c[3])
        : "r"(a[0]), "r"(a[1]), "r"(a[2]), "r"(a[3]), "r"(b[0]), "r"(b[1]));
}
__device__ __forceinline__ unsigned packbf(float lo, float hi) {
    unsigned d; asm("cvt.rn.bf16x2.f32 %0, %1, %2;" : "=r"(d) : "f"(hi), "f"(lo)); return d;
}

// ============ prep: weight cvt + rope table + bias table (no smem) ==========
__global__ __launch_bounds__(256) void prep_kernel(const float* __restrict__ w0,
                                                   const float* __restrict__ w1,
                                                   const float* __restrict__ w2,
                                                   const float* __restrict__ w3,
                                                   const float* __restrict__ table)
{
    int blk = blockIdx.x;
    if (blk < 1024) {                        // wcvt
        int i = blk * 256 + threadIdx.x;
        g_Wh[0*Cc*Cc + i] = __float2bfloat16_rn(w0[i]);
        g_Wh[1*Cc*Cc + i] = __float2bfloat16_rn(w1[i]);
        g_Wh[2*Cc*Cc + i] = __float2bfloat16_rn(w2[i]);
        g_Wh[3*Cc*Cc + i] = __float2bfloat16_rn(w3[i]);
    } else if (blk < 1536) {                 // rope
        int i = (blk - 1024) * 256 + threadIdx.x;
        int n = i >> 5, k = i & 31;
        float invf = exp2f(-(float)k * (13.287712379549449f / 32.0f));
        float ang  = (float)n * invf;
        float sv, cv;  sincosf(ang, &sv, &cv);
        g_sin[i] = sv;  g_cos[i] = cv;
    } else {                                 // bias
        int i = (blk - 1536) * 256 + threadIdx.x;
        int h  = i >> 12;
        int qi = (i >> 6) & 63, ki = i & 63;
        int dh = (qi >> 3) - (ki >> 3) + 7;
        int dw = (qi & 7)  - (ki & 7)  + 7;
        g_bias[i] = table[(dh * 15 + dw) * NHh + h];
    }
}

// ====== layernorm: 32 tokens x 512 C per block, smem transpose ======
template<bool F32OUT>
__global__ __launch_bounds__(256) void ln_kernel(const float* __restrict__ x,
                                                 const float* __restrict__ g,
                                                 const float* __restrict__ bt,
                                                 float* __restrict__ yf,
                                                 bf16* __restrict__ yh)
{
    extern __shared__ float sm[];
    float* sx  = sm;                  // [512][33]
    float* ps  = sm + 512*33;         // [8][32]
    float* ps2 = ps + 256;            // [8][32]
    float* smu = ps2 + 256;           // [32]
    float* sin_ = smu + 32;           // [32] inv

    const int blk = blockIdx.x;       // 0..1023
    const int b   = blk >> 7;
    const int n0  = (blk & 127) * 32;
    const int tid = threadIdx.x;
    const int t   = tid & 31;
    const int cp  = tid >> 5;

    const float* xb = x + (size_t)b*Cc*Nn + n0;
    float s = 0.f, s2 = 0.f;
#pragma unroll 8
    for (int it = 0; it < 64; it++) {
        int c = it*8 + cp;
        float v = xb[(size_t)c*Nn + t];
        sx[c*33 + t] = v;
        s += v;  s2 = fmaf(v, v, s2);
    }
    ps[cp*32 + t] = s;  ps2[cp*32 + t] = s2;
    __syncthreads();
    if (tid < 32) {
        float a = 0.f, a2 = 0.f;
#pragma unroll
        for (int k = 0; k < 8; k++) { a += ps[k*32 + tid]; a2 += ps2[k*32 + tid]; }
        float mu  = a * (1.f/Cc);
        float var = a2 * (1.f/Cc) - mu*mu;
        smu[tid]  = mu;
        sin_[tid] = rsqrtf(var + EPSf);
    }
    __syncthreads();

    const float mu = smu[t], inv = sin_[t];
    float* yfb = F32OUT ? (yf + (size_t)b*Cc*Nn + n0) : nullptr;
#pragma unroll 8
    for (int it = 0; it < 64; it++) {
        int c = it*8 + cp;
        float o = (sx[c*33 + t] - mu) * inv * g[c] + bt[c];
        sx[c*33 + t] = o;
        if (F32OUT) yfb[(size_t)c*Nn + t] = o;
    }
    __syncthreads();

    {
        int tok = tid & 31, cb = (tid >> 5) * 64;
        union { uint4 q[8]; unsigned u[32]; } buf;
#pragma unroll
        for (int i = 0; i < 32; i++) {
            float v0 = sx[(cb + 2*i    )*33 + tok];
            float v1 = sx[(cb + 2*i + 1)*33 + tok];
            buf.u[i] = packbf(v0, v1);
        }
        uint4* dst = (uint4*)(yh + ((size_t)b*Nn + n0 + tok)*Cc + cb);
#pragma unroll
        for (int i = 0; i < 8; i++) dst[i] = buf.q[i];
    }
}

// ================= bf16 GEMM (NT): merged Q/K/V projections ==================
// BK=64, 3-stage cp.async, 8 stages. smem buffers [128][72] per operand.
// grid (12, 256): x = seg/j0 (fast -> A-tile L2 reuse), y = t0.
__global__ __launch_bounds__(256, 2) void gemm_qkv_bf(const bf16* __restrict__ Aq,
                                                      const bf16* __restrict__ Akv,
                                                      const float* __restrict__ bq,
                                                      const float* __restrict__ bk,
                                                      const float* __restrict__ bv,
                                                      bf16* __restrict__ outQ,
                                                      bf16* __restrict__ outK,
                                                      bf16* __restrict__ outV)
{
    extern __shared__ __align__(16) bf16 smraw[];
    bf16* As = smraw;                 // 3 x 128*72
    bf16* Bs = smraw + 3*9216;        // 3 x 128*72

    const int yy  = blockIdx.x;                 // 0..11
    const int seg = yy >> 2;                    // 0=Q 1=K 2=V
    const bf16*  A    = seg ? Akv : Aq;
    const bf16*  W    = g_Wh + (size_t)seg*Cc*Cc;
    const float* bias = (seg == 0) ? bq : (seg == 1) ? bk : bv;
    bf16*        out  = (seg == 0) ? outQ : (seg == 1) ? outK : outV;
    const bool   rope = (seg < 2);
    const int j0 = (yy & 3) * 128;

    const int t0 = blockIdx.y * 128;
    const int b  = t0 >> 12;
    const int n0 = t0 & 4095;
    const int tid = threadIdx.x;
    const int lane = tid & 31, wid = tid >> 5;
    const int wm = wid & 1, wn = wid >> 1;
    const int r = lane >> 2, q = lane & 3;
    const int grp = lane >> 3, lr = lane & 7;

    float acc[4][4][4];
#pragma unroll
    for (int i = 0; i < 4; i++)
#pragma unroll
        for (int j = 0; j < 4; j++)
#pragma unroll
            for (int k = 0; k < 4; k++) acc[i][j][k] = 0.f;

#define LOAD_QKV(S, BUF)                                                        \
    {                                                                           \
        bf16* Ad = As + (BUF)*9216;                                             \
        bf16* Bd = Bs + (BUF)*9216;                                             \
        int c0 = (S)*64;                                                        \
        _Pragma("unroll")                                                       \
        for (int u = 0; u < 4; u++) {                                           \
            int flat = u*256 + tid;                                             \
            int m = flat >> 3, kc = flat & 7;                                   \
            CP16(sptr(Ad + m*72 + kc*8),                                        \
                 A + (size_t)(t0+m)*Cc + c0 + kc*8);                            \
            CP16(sptr(Bd + m*72 + kc*8),                                        \
                 W + (size_t)(j0+m)*Cc + c0 + kc*8);                            \
        }                                                                       \
    }

    LOAD_QKV(0, 0); CP_COMMIT();
    LOAD_QKV(1, 1); CP_COMMIT();

#pragma unroll 1
    for (int s = 0; s < 8; s++) {
        if (s < 7) { CP_WAIT(1); } else { CP_WAIT(0); }
        __syncthreads();
        if (s < 6) { LOAD_QKV(s+2, (s+2)%3); CP_COMMIT(); }

        const bf16* Ac = As + (s%3)*9216;
        const bf16* Bc = Bs + (s%3)*9216;
#pragma unroll
        for (int kk = 0; kk < 4; kk++) {
            unsigned af[4][4], bfr[4][2];
#pragma unroll
            for (int i = 0; i < 4; i++) {
                int m  = wm*64 + 16*i + ((grp & 1) ? 8 : 0) + lr;
                int ka = (grp & 2) ? 8 : 0;
                ldsm_x4(af[i][0], af[i][1], af[i][2], af[i][3],
                        sptr(Ac + m*72 + kk*16 + ka));
            }
#pragma unroll
            for (int jg = 0; jg < 2; jg++) {
                int n = wn*32 + jg*16 + ((grp & 2) ? 8 : 0) + lr;
                int ka = (grp & 1) ? 8 : 0;
                ldsm_x4(bfr[jg*2][0], bfr[jg*2][1], bfr[jg*2+1][0], bfr[jg*2+1][1],
                        sptr(Bc + n*72 + kk*16 + ka));
            }
#pragma unroll
            for (int i = 0; i < 4; i++)
#pragma unroll
                for (int j = 0; j < 4; j++)
                    mma_bf16(acc[i][j], af[i], bfr[j]);
        }
    }
#undef LOAD_QKV

    // ---- epilogue: bias (+ RoPE, fp32), store bf16 ----
#pragma unroll
    for (int i = 0; i < 4; i++) {
        int ntok = n0 + wm*64 + 16*i + r;
#pragma unroll
        for (int j = 0; j < 4; j++) {
            int jj = j0 + wn*32 + 8*j + 2*q;
            int hh = jj >> 6;
            int d  = jj & 63;                  // even
            float bv0 = bias[jj], bv1 = bias[jj+1];
#pragma unroll
            for (int half = 0; half < 2; half++) {
                int n = ntok + 8*half;
                float v0 = acc[i][j][2*half+0] + bv0;
                float v1 = acc[i][j][2*half+1] + bv1;
                float x, y;
                if (rope) {
                    int p = (n << 5) + (d >> 1);
                    float sv = g_sin[p], cv = g_cos[p];
                    x = v0*cv - v1*sv;
                    y = v0*sv + v1*cv;
                } else { x = v0; y = v1; }
                *(__nv_bfloat162*)&out[(((size_t)b*NHh + hh)*Nn + n)*Dd + d] =
                    __floats2bfloat162_rn(x, y);
            }
        }
    }
}

// ================= bf16 GEMM (NT): output projection, BK=64 ==================
// grid (4, 256): x = j0 (fast -> A-tile L2 reuse), y = t0.
// Coalesced epilogue: acc staged through smem [128][132] fp32, then
// warp-per-16-rows float4 streaming of resid/out.
__global__ __launch_bounds__(256, 2) void gemm_o_bf(const bf16* __restrict__ A,
                                                    const bf16* __restrict__ W,
                                                    const float* __restrict__ bias,
                                                    const float* __restrict__ resid,
                                                    float* __restrict__ out)
{
    extern __shared__ __align__(16) bf16 smraw[];
    bf16* As = smraw;                 // 3 x 128*72
    bf16* Bs = smraw + 3*9216;        // 3 x 128*72

    const int t0 = blockIdx.y * 128;
    const int b  = t0 >> 12;
    const int n0 = t0 & 4095;
    const int j0 = blockIdx.x * 128;
    const int tid = threadIdx.x;
    const int lane = tid & 31, wid = tid >> 5;
    const int wm = wid & 1, wn = wid >> 1;
    const int r = lane >> 2, q = lane & 3;
    const int grp = lane >> 3, lr = lane & 7;

    float acc[4][4][4];
#pragma unroll
    for (int i = 0; i < 4; i++)
#pragma unroll
        for (int j = 0; j < 4; j++)
#pragma unroll
            for (int k = 0; k < 4; k++) acc[i][j][k] = 0.f;

#define LOAD_O(S, BUF)                                                          \
    {                                                                           \
        bf16* Ad = As + (BUF)*9216;                                             \
        bf16* Bd = Bs + (BUF)*9216;                                             \
        int c0 = (S)*64;                                                        \
        _Pragma("unroll")                                                       \
        for (int u = 0; u < 4; u++) {                                           \
            int flat = u*256 + tid;                                             \
            int m = flat >> 3, kc = flat & 7;                                   \
            CP16(sptr(Ad + m*72 + kc*8),                                        \
                 A + (size_t)(t0+m)*Cc + c0 + kc*8);                            \
            CP16(sptr(Bd + m*72 + kc*8),                                        \
                 W + (size_t)(j0+m)*Cc + c0 + kc*8);                            \
        }                                                                       \
    }

    LOAD_O(0, 0); CP_COMMIT();
    LOAD_O(1, 1); CP_COMMIT();

#pragma unroll 1
    for (int s = 0; s < 8; s++) {
        if (s < 7) { CP_WAIT(1); } else { CP_WAIT(0); }
        __syncthreads();
        if (s < 6) { LOAD_O(s+2, (s+2)%3); CP_COMMIT(); }

        const bf16* Ac = As + (s%3)*9216;
        const bf16* Bc = Bs + (s%3)*9216;
#pragma unroll
        for (int kk = 0; kk < 4; kk++) {
            unsigned af[4][4], bfr[4][2];
#pragma unroll
            for (int i = 0; i < 4; i++) {
                int m  = wm*64 + 16*i + ((grp & 1) ? 8 : 0) + lr;
                int ka = (grp & 2) ? 8 : 0;
                ldsm_x4(af[i][0], af[i][1], af[i][2], af[i][3],
                        sptr(Ac + m*72 + kk*16 + ka));
            }
#pragma unroll
            for (int jg = 0; jg < 2; jg++) {
                int n = wn*32 + jg*16 + ((grp & 2) ? 8 : 0) + lr;
                int ka = (grp & 1) ? 8 : 0;
                ldsm_x4(bfr[jg*2][0], bfr[jg*2][1], bfr[jg*2+1][0], bfr[jg*2+1][1],
                        sptr(Bc + n*72 + kk*16 + ka));
            }
#pragma unroll
            for (int i = 0; i < 4; i++)
#pragma unroll
                for (int j = 0; j < 4; j++)
                    mma_bf16(acc[i][j], af[i], bfr[j]);
        }
    }
#undef LOAD_O

    // ---- coalesced epilogue: stage acc in smem, then float4 stream ----
    __syncthreads();                       // all LDSM reads of last stage done
    float* sacc = (float*)smraw;           // [128][132] fp32 = 67584 B
#pragma unroll
    for (int i = 0; i < 4; i++) {
#pragma unroll
        for (int j = 0; j < 4; j++) {
#pragma unroll
            for (int half = 0; half < 2; half++) {
#pragma unroll
                for (int col = 0; col < 2; col++) {
                    int row = wn*32 + 8*j + 2*q + col;
                    int n   = wm*64 + 16*i + r + 8*half;
                    sacc[row*132 + n] = acc[i][j][2*half + col];
                }
            }
        }
    }
    __syncthreads();

    {
        int row0 = wid * 16;
#pragma unroll
        for (int rr = 0; rr < 16; rr++) {
            int row = row0 + rr;
            int jj  = j0 + row;
            float bj = bias[jj];
            int n = n0 + lane*4;
            size_t o = ((size_t)b*Cc + jj)*Nn + n;
            float4 v   = *(float4*)&sacc[row*132 + lane*4];
            float4 res = *(const float4*)&resid[o];
            v.x += bj + res.x;  v.y += bj + res.y;
            v.z += bj + res.z;  v.w += bj + res.w;
            *(float4*)&out[o] = v;
        }
    }
}

// ---------------- windowed attention (bf16 mma), 1 block per (head, window) --
// 4 warps; inputs staged with cp.async (no LDG->STS register round trip).
__global__ __launch_bounds__(128) void attn_bf()
{
    __shared__ __align__(16) bf16 Qs[64*72];
    __shared__ __align__(16) bf16 Ks[64*72];
    __shared__ __align__(16) bf16 Vs[64*72];

    const int bx  = blockIdx.x;     // 0..4095
    const int h   = bx >> 9;
    const int win = bx & 511;
    const int b   = win >> 6;
    const int w   = win & 63;
    const int wy  = w >> 3, wx = w & 7;
    const int tid = threadIdx.x;
    const int lane = tid & 31, wid = tid >> 5;
    const int grp = lane >> 3, lr = lane & 7;

    {
        int t  = tid & 63;
        int c2 = tid >> 6;
        int n_t = ((wy*8 + (t >> 3)) << 6) + wx*8 + (t & 7);
        size_t base = (((size_t)b*NHh + h)*Nn + n_t)*Dd;
#pragma unroll
        for (int u = 0; u < 4; u++) {
            int off = c2*32 + u*8;
            CP16(sptr((char*)Qs + (t*72 + off)*2), g_Qh + base + off);
            CP16(sptr((char*)Ks + (t*72 + off)*2), g_Kh + base + off);
            CP16(sptr((char*)Vs + (t*72 + off)*2), g_Vh + base + off);
        }
        CP_COMMIT();
        CP_WAIT(0);
    }
    __syncthreads();

    const int m0 = wid * 16;

    unsigned af[4][4];
#pragma unroll
    for (int kk = 0; kk < 4; kk++) {
        int m  = m0 + ((grp & 1) ? 8 : 0) + lr;
        int ka = (grp & 2) ? 8 : 0;
        ldsm_x4(af[kk][0], af[kk][1], af[kk][2], af[kk][3],
                sptr(Qs + m*72 + kk*16 + ka));
    }

    float s[8][4];
#pragma unroll
    for (int j = 0; j < 8; j++)
#pragma unroll
        for (int c = 0; c < 4; c++) s[j][c] = 0.f;

#pragma unroll
    for (int kk = 0; kk < 4; kk++) {
        unsigned bfr[8][2];
#pragma unroll
        for (int jg = 0; jg < 4; jg++) {
            int n  = jg*16 + ((grp & 2) ? 8 : 0) + lr;
            int ka = (grp & 1) ? 8 : 0;
            ldsm_x4(bfr[jg*2][0], bfr[jg*2][1], bfr[jg*2+1][0], bfr[jg*2+1][1],
                    sptr(Ks + n*72 + kk*16 + ka));
        }
#pragma unroll
        for (int j = 0; j < 8; j++)
            mma_bf16(s[j], af[kk], bfr[j]);
    }

    const float* bh = g_bias + (h << 12);
    const int row0 = m0 + (lane >> 2);
    const int col0 = 2 * (lane & 3);
    float mx0 = -1e30f, mx1 = -1e30f;
#pragma unroll
    for (int j = 0; j < 8; j++) {
        float2 b0 = *(const float2*)(bh + row0*64 + 8*j + col0);
        float2 b1 = *(const float2*)(bh + (row0+8)*64 + 8*j + col0);
        s[j][0] = fmaf(s[j][0], 0.125f, b0.x);
        s[j][1] = fmaf(s[j][1], 0.125f, b0.y);
        s[j][2] = fmaf(s[j][2], 0.125f, b1.x);
        s[j][3] = fmaf(s[j][3], 0.125f, b1.y);
        mx0 = fmaxf(mx0, fmaxf(s[j][0], s[j][1]));
        mx1 = fmaxf(mx1, fmaxf(s[j][2], s[j][3]));
    }
    mx0 = fmaxf(mx0, __shfl_xor_sync(0xffffffffu, mx0, 1));
    mx0 = fmaxf(mx0, __shfl_xor_sync(0xffffffffu, mx0, 2));
    mx1 = fmaxf(mx1, __shfl_xor_sync(0xffffffffu, mx1, 1));
    mx1 = fmaxf(mx1, __shfl_xor_sync(0xffffffffu, mx1, 2));

    float sum0 = 0.f, sum1 = 0.f;
#pragma unroll
    for (int j = 0; j < 8; j++) {
        s[j][0] = __expf(s[j][0] - mx0);
        s[j][1] = __expf(s[j][1] - mx0);
        s[j][2] = __expf(s[j][2] - mx1);
        s[j][3] = __expf(s[j][3] - mx1);
        sum0 += s[j][0] + s[j][1];
        sum1 += s[j][2] + s[j][3];
    }
    sum0 += __shfl_xor_sync(0xffffffffu, sum0, 1);
    sum0 += __shfl_xor_sync(0xffffffffu, sum0, 2);
    sum1 += __shfl_xor_sync(0xffffffffu, sum1, 1);
    sum1 += __shfl_xor_sync(0xffffffffu, sum1, 2);
    float inv0 = 1.f / sum0, inv1 = 1.f / sum1;

    float o[8][4];
#pragma unroll
    for (int j = 0; j < 8; j++)
#pragma unroll
        for (int c = 0; c < 4; c++) o[j][c] = 0.f;

#pragma unroll
    for (int kk = 0; kk < 4; kk++) {
        unsigned pa[4];
        pa[0] = packbf(s[2*kk  ][0], s[2*kk  ][1]);
        pa[1] = packbf(s[2*kk  ][2], s[2*kk  ][3]);
        pa[2] = packbf(s[2*kk+1][0], s[2*kk+1][1]);
        pa[3] = packbf(s[2*kk+1][2], s[2*kk+1][3]);
        unsigned vb[8][2];
#pragma unroll
        for (int jg = 0; jg < 4; jg++) {
            int rowk = kk*16 + ((grp & 1) ? 8 : 0) + lr;
            int cold = jg*16 + ((grp & 2) ? 8 : 0);
            ldsm_x4t(vb[jg*2][0], vb[jg*2][1], vb[jg*2+1][0], vb[jg*2+1][1],
                     sptr(Vs + rowk*72 + cold));
        }
#pragma unroll
        for (int j = 0; j < 8; j++)
            mma_bf16(o[j], pa, vb[j]);
    }

    {
        int tA = row0, tB = row0 + 8;
        int nA = ((wy*8 + (tA >> 3)) << 6) + wx*8 + (tA & 7);
        int nB = ((wy*8 + (tB >> 3)) << 6) + wx*8 + (tB & 7);
        size_t baseA = ((size_t)b*Nn + nA)*Cc + (h << 6);
        size_t baseB = ((size_t)b*Nn + nB)*Cc + (h << 6);
#pragma unroll
        for (int j = 0; j < 8; j++) {
            int d = 8*j + col0;
            *(__nv_bfloat162*)&g_AOh[baseA + d] =
                __floats2bfloat162_rn(o[j][0]*inv0, o[j][1]*inv0);
            *(__nv_bfloat162*)&g_AOh[baseB + d] =
                __floats2bfloat162_rn(o[j][2]*inv1, o[j][3]*inv1);
        }
    }
}

// ---------------- host side ----------------
extern "C" void kernel_launch(void* const* d_in, const int* in_sizes, int n_in,
                              void* d_out, int out_size)
{
    const float* q    = (const float*)d_in[0];
    const float* kv   = (const float*)d_in[1];
    const float* gq   = (const float*)d_in[2];
    const float* bqln = (const float*)d_in[3];
    const float* gkv  = (const float*)d_in[4];
    const float* bkvln= (const float*)d_in[5];
    const float* Wq   = (const float*)d_in[6];
    const float* bq   = (const float*)d_in[7];
    const float* Wk   = (const float*)d_in[8];
    const float* bk   = (const float*)d_in[9];
    const float* Wv   = (const float*)d_in[10];
    const float* bv   = (const float*)d_in[11];
    const float* Wo   = (const float*)d_in[12];
    const float* bo   = (const float*)d_in[13];
    const float* tbl  = (const float*)d_in[14];
    float* out = (float*)d_out;

    void* p;
    cudaGetSymbolAddress(&p, g_qn);   float* qn   = (float*)p;
    cudaGetSymbolAddress(&p, g_qnt);  bf16* qnt   = (bf16*)p;
    cudaGetSymbolAddress(&p, g_kvnt); bf16* kvnt  = (bf16*)p;
    cudaGetSymbolAddress(&p, g_Wh);   bf16* Wh    = (bf16*)p;
    cudaGetSymbolAddress(&p, g_Qh);   bf16* Qb    = (bf16*)p;
    cudaGetSymbolAddress(&p, g_Kh);   bf16* Kb    = (bf16*)p;
    cudaGetSymbolAddress(&p, g_Vh);   bf16* Vb    = (bf16*)p;
    cudaGetSymbolAddress(&p, g_AOh);  bf16* AO    = (bf16*)p;

    const int SMEM_LN = (512*33 + 512 + 64) * 4;     // 69888 B
    const int SMEM_G  = (6*9216) * 2;                // 110592 B
    static int smem_set = 0;
    if (!smem_set) {
        cudaFuncSetAttribute(ln_kernel<true>,  cudaFuncAttributeMaxDynamicSharedMemorySize, SMEM_LN);
        cudaFuncSetAttribute(ln_kernel<false>, cudaFuncAttributeMaxDynamicSharedMemorySize, SMEM_LN);
        cudaFuncSetAttribute(gemm_qkv_bf,      cudaFuncAttributeMaxDynamicSharedMemorySize, SMEM_G);
        cudaFuncSetAttribute(gemm_o_bf,        cudaFuncAttributeMaxDynamicSharedMemorySize, SMEM_G);
        smem_set = 1;
    }

    // 0: weight cvt + rope + bias tables (tiny, no smem)
    prep_kernel<<<1664, 256>>>(Wq, Wk, Wv, Wo, tbl);

    // 1,2: layernorms (token-major bf16 out; q also fp32 channel-major)
    ln_kernel<true ><<<1024, 256, SMEM_LN>>>(q,  gq,  bqln,  qn, qnt);
    ln_kernel<false><<<1024, 256, SMEM_LN>>>(kv, gkv, bkvln, qn, kvnt);

    // 3: merged Q/K/V projections (rope fused for Q and K); x fast = A reuse
    gemm_qkv_bf<<<dim3(12, 256), 256, SMEM_G>>>(qnt, kvnt, bq, bk, bv, Qb, Kb, Vb);

    // 4: windowed attention (4 warps, cp.async staging)
    attn_bf<<<NHh * Bb * 64, 128>>>();

    // 5: output projection + bias + residual -> (B,C,H,W), coalesced epilogue
    gemm_o_bf<<<dim3(4, 256), 256, SMEM_G>>>(AO, Wh + 3*Cc*Cc, bo, qn, out);
}